// round 1
// baseline (speedup 1.0000x reference)
#include <cuda_runtime.h>
#include <cstdint>

#define HH 128
#define WW 128
#define HWS 16384
#define CHN 256
#define NB 4

// Scratch (device globals — allocation-free rule)
__device__ float g_q[(size_t)NB * 32 * HWS];   // [B][32][H][W]
__device__ float g_k[(size_t)NB * 32 * HWS];   // [B][32][H][W]
__device__ float g_v[(size_t)NB * 256 * HWS];  // [B][256][H][W]

// ---------------------------------------------------------------------------
// Projection GEMMs: out[o][p] = sum_c W[o][c] * x[b][c][p] + bias[o]
// BM=64, BN=64, BK=16, 256 threads, 4x4 micro-tile per thread.
// ---------------------------------------------------------------------------
__global__ void proj_qk_kernel(const float* __restrict__ x,
                               const float* __restrict__ Wq, const float* __restrict__ bq,
                               const float* __restrict__ Wk, const float* __restrict__ bk)
{
    __shared__ float Ws[16][65];
    __shared__ __align__(16) float Xs[16][64];
    const int b = blockIdx.z;
    const int p0 = blockIdx.x * 64;
    const int tid = threadIdx.x;
    const int tx = tid & 15, ty = tid >> 4;
    const float* xb = x + (size_t)b * CHN * HWS;
    float acc[4][4] = {};

    for (int k0 = 0; k0 < 256; k0 += 16) {
        #pragma unroll
        for (int r = 0; r < 4; r++) {
            int idx = tid + r * 256;           // 0..1023
            int o = idx >> 4, kk = idx & 15;
            Ws[kk][o] = (o < 32) ? Wq[o * 256 + k0 + kk]
                                 : Wk[(o - 32) * 256 + k0 + kk];
        }
        #pragma unroll
        for (int r = 0; r < 4; r++) {
            int idx = tid + r * 256;
            int kk = idx >> 6, p = idx & 63;
            Xs[kk][p] = xb[(size_t)(k0 + kk) * HWS + p0 + p];
        }
        __syncthreads();
        #pragma unroll
        for (int kk = 0; kk < 16; kk++) {
            float a0 = Ws[kk][ty * 4 + 0];
            float a1 = Ws[kk][ty * 4 + 1];
            float a2 = Ws[kk][ty * 4 + 2];
            float a3 = Ws[kk][ty * 4 + 3];
            float4 xv = *(const float4*)&Xs[kk][tx * 4];
            acc[0][0] += a0 * xv.x; acc[0][1] += a0 * xv.y; acc[0][2] += a0 * xv.z; acc[0][3] += a0 * xv.w;
            acc[1][0] += a1 * xv.x; acc[1][1] += a1 * xv.y; acc[1][2] += a1 * xv.z; acc[1][3] += a1 * xv.w;
            acc[2][0] += a2 * xv.x; acc[2][1] += a2 * xv.y; acc[2][2] += a2 * xv.z; acc[2][3] += a2 * xv.w;
            acc[3][0] += a3 * xv.x; acc[3][1] += a3 * xv.y; acc[3][2] += a3 * xv.z; acc[3][3] += a3 * xv.w;
        }
        __syncthreads();
    }
    #pragma unroll
    for (int m = 0; m < 4; m++) {
        int o = ty * 4 + m;
        float bias;
        float* dst;
        if (o < 32) { bias = bq[o]; dst = &g_q[((size_t)b * 32 + o) * HWS]; }
        else        { bias = bk[o - 32]; dst = &g_k[((size_t)b * 32 + (o - 32)) * HWS]; }
        float4 v = make_float4(acc[m][0] + bias, acc[m][1] + bias,
                               acc[m][2] + bias, acc[m][3] + bias);
        *(float4*)&dst[p0 + tx * 4] = v;
    }
}

__global__ void proj_v_kernel(const float* __restrict__ x,
                              const float* __restrict__ Wv, const float* __restrict__ bv)
{
    __shared__ float Ws[16][65];
    __shared__ __align__(16) float Xs[16][64];
    const int b = blockIdx.z;
    const int p0 = blockIdx.x * 64;
    const int o0 = blockIdx.y * 64;
    const int tid = threadIdx.x;
    const int tx = tid & 15, ty = tid >> 4;
    const float* xb = x + (size_t)b * CHN * HWS;
    float acc[4][4] = {};

    for (int k0 = 0; k0 < 256; k0 += 16) {
        #pragma unroll
        for (int r = 0; r < 4; r++) {
            int idx = tid + r * 256;
            int o = idx >> 4, kk = idx & 15;
            Ws[kk][o] = Wv[(size_t)(o0 + o) * 256 + k0 + kk];
        }
        #pragma unroll
        for (int r = 0; r < 4; r++) {
            int idx = tid + r * 256;
            int kk = idx >> 6, p = idx & 63;
            Xs[kk][p] = xb[(size_t)(k0 + kk) * HWS + p0 + p];
        }
        __syncthreads();
        #pragma unroll
        for (int kk = 0; kk < 16; kk++) {
            float a0 = Ws[kk][ty * 4 + 0];
            float a1 = Ws[kk][ty * 4 + 1];
            float a2 = Ws[kk][ty * 4 + 2];
            float a3 = Ws[kk][ty * 4 + 3];
            float4 xv = *(const float4*)&Xs[kk][tx * 4];
            acc[0][0] += a0 * xv.x; acc[0][1] += a0 * xv.y; acc[0][2] += a0 * xv.z; acc[0][3] += a0 * xv.w;
            acc[1][0] += a1 * xv.x; acc[1][1] += a1 * xv.y; acc[1][2] += a1 * xv.z; acc[1][3] += a1 * xv.w;
            acc[2][0] += a2 * xv.x; acc[2][1] += a2 * xv.y; acc[2][2] += a2 * xv.z; acc[2][3] += a2 * xv.w;
            acc[3][0] += a3 * xv.x; acc[3][1] += a3 * xv.y; acc[3][2] += a3 * xv.z; acc[3][3] += a3 * xv.w;
        }
        __syncthreads();
    }
    #pragma unroll
    for (int m = 0; m < 4; m++) {
        int o = o0 + ty * 4 + m;
        float bias = bv[o];
        float* dst = &g_v[((size_t)b * 256 + o) * HWS];
        float4 v = make_float4(acc[m][0] + bias, acc[m][1] + bias,
                               acc[m][2] + bias, acc[m][3] + bias);
        *(float4*)&dst[p0 + tx * 4] = v;
    }
}

// ---------------------------------------------------------------------------
// Fused criss-cross attention. Block (i, bh) computes row-attention for row i
// (phase 0) and column-attention for column i (phase 1); the reference's o_v
// transpose means both land on output row i. acc persists across phases.
// SMEM: E[128][128] (stored [g][j] so softmax + O reads are conflict-free),
// V[64][128], Q[8][128], K[8][128], red[256].  107,520 B -> 2 blocks/SM.
// ---------------------------------------------------------------------------
__global__ void attn_kernel(const float* __restrict__ x,
                            const float* __restrict__ gamma,
                            float* __restrict__ out)
{
    extern __shared__ __align__(16) float smem[];
    float* E   = smem;               // 16384 floats, layout E[g*128 + j]
    float* Vs  = E + 16384;          // 8192  floats, Vs[c*128 + g]
    float* Qs  = Vs + 8192;          // 1024
    float* Ks  = Qs + 1024;          // 1024
    float* red = Ks + 1024;          // 256

    const int i  = blockIdx.x;       // row (phase 0) / column (phase 1) index
    const int bh = blockIdx.y;
    const int b = bh >> 2, h = bh & 3;
    const int tid = threadIdx.x;
    const int j = tid & 127;
    const int half = tid >> 7;       // 0 or 1
    const int g0 = half * 64;
    const int cb = half * 32;

    float acc[32];
    #pragma unroll
    for (int c = 0; c < 32; c++) acc[c] = 0.0f;

    const size_t qk_base = ((size_t)b * 32 + h * 8) * HWS;
    const size_t v_base  = ((size_t)b * 256 + h * 64) * HWS;

    for (int phase = 0; phase < 2; phase++) {
        // ---- load line of q, k, v into smem ----
        if (phase == 0) {
            for (int idx = tid; idx < 1024; idx += 256) {
                int c = idx >> 7, w = idx & 127;
                size_t off = qk_base + ((size_t)c * HH + i) * WW + w;
                Qs[idx] = g_q[off];
                Ks[idx] = g_k[off];
            }
            for (int idx = tid; idx < 8192; idx += 256) {
                int c = idx >> 7, w = idx & 127;
                Vs[idx] = g_v[v_base + ((size_t)c * HH + i) * WW + w];
            }
        } else {
            for (int idx = tid; idx < 1024; idx += 256) {
                int c = idx >> 7, r = idx & 127;
                size_t off = qk_base + ((size_t)c * HH + r) * WW + i;
                Qs[idx] = g_q[off];
                Ks[idx] = g_k[off];
            }
            for (int idx = tid; idx < 8192; idx += 256) {
                int c = idx >> 7, r = idx & 127;
                Vs[idx] = g_v[v_base + ((size_t)c * HH + r) * WW + i];
            }
        }
        __syncthreads();

        // ---- energies: E[g][j] = sum_c Q[c][j] * K[c][g] ----
        float qr[8];
        #pragma unroll
        for (int c = 0; c < 8; c++) qr[c] = Qs[c * 128 + j];
        for (int g = g0; g < g0 + 64; g++) {
            float e = 0.0f;
            #pragma unroll
            for (int c = 0; c < 8; c++) e += qr[c] * Ks[c * 128 + g];
            E[g * 128 + j] = e;
        }
        __syncthreads();

        // ---- softmax over g (2 threads per j cooperate) ----
        float m = -1e30f;
        for (int g = g0; g < g0 + 64; g++) m = fmaxf(m, E[g * 128 + j]);
        red[tid] = m;
        __syncthreads();
        m = fmaxf(red[j], red[j + 128]);
        float s = 0.0f;
        for (int g = g0; g < g0 + 64; g++) {
            float p = __expf(E[g * 128 + j] - m);
            E[g * 128 + j] = p;
            s += p;
        }
        __syncthreads();
        red[tid] = s;
        __syncthreads();
        const float is = 1.0f / (red[j] + red[j + 128]);

        // ---- O: acc[c] += sum_g (E[g][j]*is) * V[c][g] ----
        for (int g = 0; g < 128; g += 4) {
            float a0 = E[(g + 0) * 128 + j] * is;
            float a1 = E[(g + 1) * 128 + j] * is;
            float a2 = E[(g + 2) * 128 + j] * is;
            float a3 = E[(g + 3) * 128 + j] * is;
            #pragma unroll
            for (int c = 0; c < 32; c++) {
                const float4 v4 = *(const float4*)&Vs[(cb + c) * 128 + g];
                acc[c] += a0 * v4.x + a1 * v4.y + a2 * v4.z + a3 * v4.w;
            }
        }
        __syncthreads();   // protect smem before next phase's loads
    }

    // ---- epilogue: out = gamma * (o_h + o_v) + x, row i ----
    const float gm = gamma[0];
    #pragma unroll
    for (int c = 0; c < 32; c++) {
        size_t off = (((size_t)b * 256 + h * 64 + cb + c) * HH + i) * WW + j;
        out[off] = gm * acc[c] + x[off];
    }
}

// ---------------------------------------------------------------------------
extern "C" void kernel_launch(void* const* d_in, const int* in_sizes, int n_in,
                              void* d_out, int out_size)
{
    const float* x     = (const float*)d_in[0];
    const float* Wq    = (const float*)d_in[1];
    const float* bq    = (const float*)d_in[2];
    const float* Wk    = (const float*)d_in[3];
    const float* bk    = (const float*)d_in[4];
    const float* Wv    = (const float*)d_in[5];
    const float* bv    = (const float*)d_in[6];
    const float* gamma = (const float*)d_in[7];
    float* out = (float*)d_out;

    const int smem_bytes = (16384 + 8192 + 1024 + 1024 + 256) * 4;  // 107,520
    cudaFuncSetAttribute(attn_kernel, cudaFuncAttributeMaxDynamicSharedMemorySize,
                         smem_bytes);

    proj_qk_kernel<<<dim3(HWS / 64, 1, NB), 256>>>(x, Wq, bq, Wk, bk);
    proj_v_kernel<<<dim3(HWS / 64, 256 / 64, NB), 256>>>(x, Wv, bv);
    attn_kernel<<<dim3(HH, NB * 4), 256, smem_bytes>>>(x, gamma, out);
}

// round 4
// speedup vs baseline: 1.3242x; 1.3242x over previous
#include <cuda_runtime.h>
#include <cuda_bf16.h>
#include <cstdint>

#define HH 128
#define WW 128
#define HWS 16384
#define NB 4
#define KP 768   // split-K: [Whi|Whi|Wlo] x [Xhi|Xlo|Xhi]

// ---------------- scratch (device globals; allocation-free rule) ------------
__device__ float g_q[(size_t)NB * 32 * HWS];
__device__ float g_k[(size_t)NB * 32 * HWS];
__device__ float g_v[(size_t)NB * 256 * HWS];
__device__ __align__(16) __nv_bfloat16 g_wsplit[(size_t)384 * KP];       // [m][k']
__device__ __align__(16) __nv_bfloat16 g_xt[(size_t)NB * HWS * KP];      // [b][p][k']

// single TU-wide dynamic smem symbol (char; cast per-kernel)
extern __shared__ __align__(1024) char smem_raw[];

static __device__ __forceinline__ uint32_t sw128(uint32_t off) {
    return off ^ ((off >> 3) & 0x70);
}
__device__ __forceinline__ uint32_t smem_u32(const void* p) {
    uint32_t a;
    asm("{ .reg .u64 t; cvta.to.shared.u64 t, %1; cvt.u32.u64 %0, t; }"
        : "=r"(a) : "l"(p));
    return a;
}
__device__ __forceinline__ void ldmatrix_x4(uint32_t& r0, uint32_t& r1,
                                            uint32_t& r2, uint32_t& r3, uint32_t addr) {
    asm volatile("ldmatrix.sync.aligned.m8n8.x4.shared.b16 {%0,%1,%2,%3}, [%4];"
                 : "=r"(r0), "=r"(r1), "=r"(r2), "=r"(r3) : "r"(addr));
}
__device__ __forceinline__ void mma_bf16(float& d0, float& d1, float& d2, float& d3,
                                         uint32_t a0, uint32_t a1, uint32_t a2, uint32_t a3,
                                         uint32_t b0, uint32_t b1) {
    asm volatile("mma.sync.aligned.m16n8k16.row.col.f32.bf16.bf16.f32 "
                 "{%0,%1,%2,%3}, {%4,%5,%6,%7}, {%8,%9}, {%0,%1,%2,%3};"
                 : "+f"(d0), "+f"(d1), "+f"(d2), "+f"(d3)
                 : "r"(a0), "r"(a1), "r"(a2), "r"(a3), "r"(b0), "r"(b1));
}

// ---------------------------------------------------------------------------
// prep_w: W' bf16 [384][768]; rows 0-255 Wv, 256-287 Wq, 288-319 Wk, 320-383 0
// cols: [0:256)=hi, [256:512)=hi, [512:768)=lo
// ---------------------------------------------------------------------------
__global__ void prep_w_kernel(const float* __restrict__ Wq, const float* __restrict__ Wk,
                              const float* __restrict__ Wv)
{
    const int m = blockIdx.x;
    const int c = threadIdx.x;
    float w = 0.0f;
    if (m < 256)      w = Wv[m * 256 + c];
    else if (m < 288) w = Wq[(m - 256) * 256 + c];
    else if (m < 320) w = Wk[(m - 288) * 256 + c];
    __nv_bfloat16 hi = __float2bfloat16(w);
    __nv_bfloat16 lo = __float2bfloat16(w - __bfloat162float(hi));
    g_wsplit[(size_t)m * KP + c]       = hi;
    g_wsplit[(size_t)m * KP + 256 + c] = hi;
    g_wsplit[(size_t)m * KP + 512 + c] = lo;
}

// ---------------------------------------------------------------------------
// prep_x: XT' bf16 [b][p][768]: cols [0:256)=hi, [256:512)=lo, [512:768)=hi
// 64c x 64p transpose tiles through smem.
// ---------------------------------------------------------------------------
__global__ void prep_x_kernel(const float* __restrict__ x)
{
    __shared__ float sm[64][65];
    const int b = blockIdx.z, ct = blockIdx.y, pt = blockIdx.x;
    const int c0 = ct * 64, p0 = pt * 64;
    const int t = threadIdx.x;
    const int pj = t & 63, ci0 = t >> 6;
    const float* xb = x + ((size_t)b * 256 + c0) * HWS + p0;
    #pragma unroll
    for (int i = 0; i < 16; i++) {
        int ci = ci0 + i * 4;
        sm[ci][pj] = xb[(size_t)ci * HWS + pj];
    }
    __syncthreads();
    const int cp = t & 31, pl = t >> 5;
    #pragma unroll
    for (int i = 0; i < 8; i++) {
        int p = pl + i * 8;
        float f0 = sm[2 * cp][p], f1 = sm[2 * cp + 1][p];
        __nv_bfloat16 h0 = __float2bfloat16(f0), h1 = __float2bfloat16(f1);
        __nv_bfloat16 l0 = __float2bfloat16(f0 - __bfloat162float(h0));
        __nv_bfloat16 l1 = __float2bfloat16(f1 - __bfloat162float(h1));
        __nv_bfloat162 hp; hp.x = h0; hp.y = h1;
        __nv_bfloat162 lp; lp.x = l0; lp.y = l1;
        __nv_bfloat16* row = g_xt + ((size_t)b * HWS + p0 + p) * KP;
        *(__nv_bfloat162*)(row + c0 + 2 * cp)       = hp;
        *(__nv_bfloat162*)(row + 256 + c0 + 2 * cp) = lp;
        *(__nv_bfloat162*)(row + 512 + c0 + 2 * cp) = hp;
    }
}

// ---------------------------------------------------------------------------
// proj_mma: D[128 m][128 p] = sum_k' W'[m][k'] * XT'[p][k'] via mma.sync bf16.
// 8 warps (2 m-halves x 4 n-quarters); each warp 64x32; K chunks of 64.
// SW128-swizzled smem tiles (row = 128B), ldmatrix.x4 operand fetch.
// ---------------------------------------------------------------------------
__global__ void __launch_bounds__(256) proj_mma_kernel(
    const float* __restrict__ bq, const float* __restrict__ bk,
    const float* __restrict__ bv)
{
    __shared__ __align__(1024) char sA[128 * 128];   // 128 m-rows x 64 bf16
    __shared__ __align__(1024) char sB[128 * 128];   // 128 p-rows x 64 bf16

    const int tid = threadIdx.x;
    const int wid = tid >> 5, lane = tid & 31;
    const int warp_m = wid & 1;          // 0,1 -> m half (64 rows)
    const int warp_n = wid >> 1;         // 0..3 -> n quarter (32 cols)
    const int pt = blockIdx.x, mt = blockIdx.y, b = blockIdx.z;

    const char* Abase = (const char*)(g_wsplit + (size_t)mt * 128 * KP);
    const char* Bbase = (const char*)(g_xt + ((size_t)b * HWS + pt * 128) * KP);
    const uint32_t sA_u = smem_u32(sA);
    const uint32_t sB_u = smem_u32(sB);

    float acc[4][4][4];
    #pragma unroll
    for (int i = 0; i < 4; i++)
        #pragma unroll
        for (int j = 0; j < 4; j++)
            #pragma unroll
            for (int k = 0; k < 4; k++) acc[i][j][k] = 0.0f;

    // precompute ldmatrix lane addressing (within-tile offsets)
    const int a_row_in = lane & 15;                 // + mi*16 + warp_m*64
    const int a_kseg   = (lane >> 4) << 4;          // 0 or 16 bytes
    const int b_row_in = (lane & 7) + ((lane >> 4) << 3);  // + ni16*16 + warp_n*32
    const int b_kseg   = ((lane >> 3) & 1) << 4;

    for (int ch = 0; ch < 12; ch++) {
        const size_t c0b = (size_t)ch * 128;        // byte offset into 1536B row
        // load A,B chunk tiles: 128 rows x 128B each
        #pragma unroll
        for (int r = 0; r < 4; r++) {
            int idx = tid + r * 256;                // 0..1023
            int row = idx >> 3, seg = idx & 7;
            uint32_t so = sw128((uint32_t)(row * 128 + seg * 16));
            *(uint4*)(sA + so) = *(const uint4*)(Abase + (size_t)row * (KP * 2) + c0b + seg * 16);
            *(uint4*)(sB + so) = *(const uint4*)(Bbase + (size_t)row * (KP * 2) + c0b + seg * 16);
        }
        __syncthreads();

        #pragma unroll
        for (int kk = 0; kk < 4; kk++) {
            uint32_t af[4][4];
            #pragma unroll
            for (int mi = 0; mi < 4; mi++) {
                int row = warp_m * 64 + mi * 16 + a_row_in;
                uint32_t addr = sA_u + sw128((uint32_t)(row * 128 + kk * 32 + a_kseg));
                ldmatrix_x4(af[mi][0], af[mi][1], af[mi][2], af[mi][3], addr);
            }
            uint32_t bf[2][4];
            #pragma unroll
            for (int ni16 = 0; ni16 < 2; ni16++) {
                int row = warp_n * 32 + ni16 * 16 + b_row_in;
                uint32_t addr = sB_u + sw128((uint32_t)(row * 128 + kk * 32 + b_kseg));
                ldmatrix_x4(bf[ni16][0], bf[ni16][1], bf[ni16][2], bf[ni16][3], addr);
            }
            #pragma unroll
            for (int mi = 0; mi < 4; mi++)
                #pragma unroll
                for (int ni = 0; ni < 4; ni++) {
                    uint32_t b0 = bf[ni >> 1][(ni & 1) * 2 + 0];
                    uint32_t b1 = bf[ni >> 1][(ni & 1) * 2 + 1];
                    mma_bf16(acc[mi][ni][0], acc[mi][ni][1], acc[mi][ni][2], acc[mi][ni][3],
                             af[mi][0], af[mi][1], af[mi][2], af[mi][3], b0, b1);
                }
        }
        __syncthreads();
    }

    // epilogue: c0,c1 -> (row, col..col+1); c2,c3 -> (row+8, col..col+1)
    const int p0 = pt * 128 + warp_n * 32 + 2 * (lane & 3);
    #pragma unroll
    for (int mi = 0; mi < 4; mi++) {
        #pragma unroll
        for (int half = 0; half < 2; half++) {
            int m = mt * 128 + warp_m * 64 + mi * 16 + (lane >> 2) + half * 8;
            float bias;
            float* dst;
            if (m < 256)      { bias = bv[m];       dst = &g_v[((size_t)b * 256 + m) * HWS]; }
            else if (m < 288) { bias = bq[m - 256]; dst = &g_q[((size_t)b * 32 + (m - 256)) * HWS]; }
            else if (m < 320) { bias = bk[m - 288]; dst = &g_k[((size_t)b * 32 + (m - 288)) * HWS]; }
            else continue;
            #pragma unroll
            for (int ni = 0; ni < 4; ni++) {
                float2 v = make_float2(acc[mi][ni][half * 2 + 0] + bias,
                                       acc[mi][ni][half * 2 + 1] + bias);
                *(float2*)&dst[p0 + ni * 8] = v;
            }
        }
    }
}

// ---------------------------------------------------------------------------
// Fused criss-cross attention (FFMA). Block (i, bh): phase 0 = row attention
// for row i, phase 1 = column attention for column i (reference's o_v
// transpose lands both on output row i). acc persists across phases.
// ---------------------------------------------------------------------------
__global__ void attn_kernel(const float* __restrict__ x,
                            const float* __restrict__ gamma,
                            float* __restrict__ out)
{
    float* smem = (float*)smem_raw;
    float* E   = smem;               // 16384 floats, E[g*128 + j]
    float* Vs  = E + 16384;          // 8192, Vs[c*128 + g]
    float* Qs  = Vs + 8192;          // 1024
    float* Ks  = Qs + 1024;          // 1024
    float* red = Ks + 1024;          // 256

    const int i  = blockIdx.x;
    const int bh = blockIdx.y;
    const int b = bh >> 2, h = bh & 3;
    const int tid = threadIdx.x;
    const int j = tid & 127;
    const int half = tid >> 7;
    const int g0 = half * 64;
    const int cb = half * 32;

    float acc[32];
    #pragma unroll
    for (int c = 0; c < 32; c++) acc[c] = 0.0f;

    const size_t qk_base = ((size_t)b * 32 + h * 8) * HWS;
    const size_t v_base  = ((size_t)b * 256 + h * 64) * HWS;

    for (int phase = 0; phase < 2; phase++) {
        if (phase == 0) {
            {
                int c = tid >> 5, w4 = tid & 31;
                size_t off = qk_base + ((size_t)c * HH + i) * WW + w4 * 4;
                *(float4*)&Qs[c * 128 + w4 * 4] = *(const float4*)&g_q[off];
                *(float4*)&Ks[c * 128 + w4 * 4] = *(const float4*)&g_k[off];
            }
            for (int idx = tid; idx < 2048; idx += 256) {
                int c = idx >> 5, w4 = idx & 31;
                *(float4*)&Vs[c * 128 + w4 * 4] =
                    *(const float4*)&g_v[v_base + ((size_t)c * HH + i) * WW + w4 * 4];
            }
        } else {
            for (int idx = tid; idx < 1024; idx += 256) {
                int c = idx >> 7, r = idx & 127;
                size_t off = qk_base + ((size_t)c * HH + r) * WW + i;
                Qs[idx] = g_q[off];
                Ks[idx] = g_k[off];
            }
            for (int idx = tid; idx < 8192; idx += 256) {
                int c = idx >> 7, r = idx & 127;
                Vs[idx] = g_v[v_base + ((size_t)c * HH + r) * WW + i];
            }
        }
        __syncthreads();

        // energies: E[g][j] = sum_c Q[c][j] * K[c][g]
        float qr[8];
        #pragma unroll
        for (int c = 0; c < 8; c++) qr[c] = Qs[c * 128 + j];
        for (int g = g0; g < g0 + 64; g += 4) {
            float4 e = make_float4(0.f, 0.f, 0.f, 0.f);
            #pragma unroll
            for (int c = 0; c < 8; c++) {
                float4 kv = *(const float4*)&Ks[c * 128 + g];
                e.x += qr[c] * kv.x; e.y += qr[c] * kv.y;
                e.z += qr[c] * kv.z; e.w += qr[c] * kv.w;
            }
            E[(g + 0) * 128 + j] = e.x;
            E[(g + 1) * 128 + j] = e.y;
            E[(g + 2) * 128 + j] = e.z;
            E[(g + 3) * 128 + j] = e.w;
        }
        __syncthreads();

        // softmax over g (2 threads per j)
        float m = -1e30f;
        for (int g = g0; g < g0 + 64; g++) m = fmaxf(m, E[g * 128 + j]);
        red[tid] = m;
        __syncthreads();
        m = fmaxf(red[j], red[j + 128]);
        float s = 0.0f;
        for (int g = g0; g < g0 + 64; g++) {
            float p = __expf(E[g * 128 + j] - m);
            E[g * 128 + j] = p;
            s += p;
        }
        __syncthreads();
        red[tid] = s;
        __syncthreads();
        const float is = 1.0f / (red[j] + red[j + 128]);

        // O: acc[c] += sum_g (E[g][j]*is) * V[c][g]
        for (int g = 0; g < 128; g += 4) {
            float a0 = E[(g + 0) * 128 + j] * is;
            float a1 = E[(g + 1) * 128 + j] * is;
            float a2 = E[(g + 2) * 128 + j] * is;
            float a3 = E[(g + 3) * 128 + j] * is;
            #pragma unroll
            for (int c = 0; c < 32; c++) {
                const float4 v4 = *(const float4*)&Vs[(cb + c) * 128 + g];
                acc[c] += a0 * v4.x + a1 * v4.y + a2 * v4.z + a3 * v4.w;
            }
        }
        __syncthreads();
    }

    const float gm = gamma[0];
    #pragma unroll
    for (int c = 0; c < 32; c++) {
        size_t off = (((size_t)b * 256 + h * 64 + cb + c) * HH + i) * WW + j;
        out[off] = gm * acc[c] + x[off];
    }
}

// ---------------------------------------------------------------------------
extern "C" void kernel_launch(void* const* d_in, const int* in_sizes, int n_in,
                              void* d_out, int out_size)
{
    const float* x     = (const float*)d_in[0];
    const float* Wq    = (const float*)d_in[1];
    const float* bq    = (const float*)d_in[2];
    const float* Wk    = (const float*)d_in[3];
    const float* bk    = (const float*)d_in[4];
    const float* Wv    = (const float*)d_in[5];
    const float* bv    = (const float*)d_in[6];
    const float* gamma = (const float*)d_in[7];
    float* out = (float*)d_out;

    const int attn_smem = (16384 + 8192 + 1024 + 1024 + 256) * 4;  // 107,520
    cudaFuncSetAttribute(attn_kernel, cudaFuncAttributeMaxDynamicSharedMemorySize,
                         attn_smem);

    prep_w_kernel<<<384, 256>>>(Wq, Wk, Wv);
    prep_x_kernel<<<dim3(256, 4, NB), 256>>>(x);
    proj_mma_kernel<<<dim3(128, 3, NB), 256>>>(bq, bk, bv);
    attn_kernel<<<dim3(HH, NB * 4), 256, attn_smem>>>(x, gamma, out);
}

// round 5
// speedup vs baseline: 1.5508x; 1.1711x over previous
#include <cuda_runtime.h>
#include <cuda_bf16.h>
#include <cstdint>

#define HH 128
#define WW 128
#define HWS 16384
#define NB 4
#define KP 768   // split-K: [Whi|Whi|Wlo] x [Xhi|Xlo|Xhi]

// ---------------- scratch (device globals; allocation-free rule) ------------
__device__ float g_q[(size_t)NB * 32 * HWS];
__device__ float g_k[(size_t)NB * 32 * HWS];
__device__ float g_v[(size_t)NB * 256 * HWS];
__device__ float g_qT[(size_t)NB * 32 * HWS];   // [b][c][W][H]
__device__ float g_kT[(size_t)NB * 32 * HWS];
__device__ float g_vT[(size_t)NB * 256 * HWS];
__device__ __align__(16) __nv_bfloat16 g_wsplit[(size_t)384 * KP];       // [m][k']
__device__ __align__(16) __nv_bfloat16 g_xt[(size_t)NB * HWS * KP];      // [b][p][k']

// single TU-wide dynamic smem symbol (char; cast per-kernel)
extern __shared__ __align__(1024) char smem_raw[];

static __device__ __forceinline__ uint32_t sw128(uint32_t off) {
    return off ^ ((off >> 3) & 0x70);
}
__device__ __forceinline__ uint32_t smem_u32(const void* p) {
    uint32_t a;
    asm("{ .reg .u64 t; cvta.to.shared.u64 t, %1; cvt.u32.u64 %0, t; }"
        : "=r"(a) : "l"(p));
    return a;
}
__device__ __forceinline__ void ldmatrix_x4(uint32_t& r0, uint32_t& r1,
                                            uint32_t& r2, uint32_t& r3, uint32_t addr) {
    asm volatile("ldmatrix.sync.aligned.m8n8.x4.shared.b16 {%0,%1,%2,%3}, [%4];"
                 : "=r"(r0), "=r"(r1), "=r"(r2), "=r"(r3) : "r"(addr));
}
__device__ __forceinline__ void mma_bf16(float& d0, float& d1, float& d2, float& d3,
                                         uint32_t a0, uint32_t a1, uint32_t a2, uint32_t a3,
                                         uint32_t b0, uint32_t b1) {
    asm volatile("mma.sync.aligned.m16n8k16.row.col.f32.bf16.bf16.f32 "
                 "{%0,%1,%2,%3}, {%4,%5,%6,%7}, {%8,%9}, {%0,%1,%2,%3};"
                 : "+f"(d0), "+f"(d1), "+f"(d2), "+f"(d3)
                 : "r"(a0), "r"(a1), "r"(a2), "r"(a3), "r"(b0), "r"(b1));
}

// ---------------------------------------------------------------------------
// prep_w: W' bf16 [384][768]; rows 0-255 Wv, 256-287 Wq, 288-319 Wk, 320-383 0
// ---------------------------------------------------------------------------
__global__ void prep_w_kernel(const float* __restrict__ Wq, const float* __restrict__ Wk,
                              const float* __restrict__ Wv)
{
    const int m = blockIdx.x;
    const int c = threadIdx.x;
    float w = 0.0f;
    if (m < 256)      w = Wv[m * 256 + c];
    else if (m < 288) w = Wq[(m - 256) * 256 + c];
    else if (m < 320) w = Wk[(m - 288) * 256 + c];
    __nv_bfloat16 hi = __float2bfloat16(w);
    __nv_bfloat16 lo = __float2bfloat16(w - __bfloat162float(hi));
    g_wsplit[(size_t)m * KP + c]       = hi;
    g_wsplit[(size_t)m * KP + 256 + c] = hi;
    g_wsplit[(size_t)m * KP + 512 + c] = lo;
}

// ---------------------------------------------------------------------------
// prep_x: XT' bf16 [b][p][768]: cols [0:256)=hi, [256:512)=lo, [512:768)=hi
// ---------------------------------------------------------------------------
__global__ void prep_x_kernel(const float* __restrict__ x)
{
    __shared__ float sm[64][65];
    const int b = blockIdx.z, ct = blockIdx.y, pt = blockIdx.x;
    const int c0 = ct * 64, p0 = pt * 64;
    const int t = threadIdx.x;
    const int pj = t & 63, ci0 = t >> 6;
    const float* xb = x + ((size_t)b * 256 + c0) * HWS + p0;
    #pragma unroll
    for (int i = 0; i < 16; i++) {
        int ci = ci0 + i * 4;
        sm[ci][pj] = xb[(size_t)ci * HWS + pj];
    }
    __syncthreads();
    const int cp = t & 31, pl = t >> 5;
    #pragma unroll
    for (int i = 0; i < 8; i++) {
        int p = pl + i * 8;
        float f0 = sm[2 * cp][p], f1 = sm[2 * cp + 1][p];
        __nv_bfloat16 h0 = __float2bfloat16(f0), h1 = __float2bfloat16(f1);
        __nv_bfloat16 l0 = __float2bfloat16(f0 - __bfloat162float(h0));
        __nv_bfloat16 l1 = __float2bfloat16(f1 - __bfloat162float(h1));
        __nv_bfloat162 hp; hp.x = h0; hp.y = h1;
        __nv_bfloat162 lp; lp.x = l0; lp.y = l1;
        __nv_bfloat16* row = g_xt + ((size_t)b * HWS + p0 + p) * KP;
        *(__nv_bfloat162*)(row + c0 + 2 * cp)       = hp;
        *(__nv_bfloat162*)(row + 256 + c0 + 2 * cp) = lp;
        *(__nv_bfloat162*)(row + 512 + c0 + 2 * cp) = hp;
    }
}

// ---------------------------------------------------------------------------
// proj_mma: D[128 m][128 p] = sum_k' W'[m][k'] * XT'[p][k'] via mma.sync bf16.
// ---------------------------------------------------------------------------
__global__ void __launch_bounds__(256) proj_mma_kernel(
    const float* __restrict__ bq, const float* __restrict__ bk,
    const float* __restrict__ bv)
{
    __shared__ __align__(1024) char sA[128 * 128];
    __shared__ __align__(1024) char sB[128 * 128];

    const int tid = threadIdx.x;
    const int wid = tid >> 5, lane = tid & 31;
    const int warp_m = wid & 1;
    const int warp_n = wid >> 1;
    const int pt = blockIdx.x, mt = blockIdx.y, b = blockIdx.z;

    const char* Abase = (const char*)(g_wsplit + (size_t)mt * 128 * KP);
    const char* Bbase = (const char*)(g_xt + ((size_t)b * HWS + pt * 128) * KP);
    const uint32_t sA_u = smem_u32(sA);
    const uint32_t sB_u = smem_u32(sB);

    float acc[4][4][4];
    #pragma unroll
    for (int i = 0; i < 4; i++)
        #pragma unroll
        for (int j = 0; j < 4; j++)
            #pragma unroll
            for (int k = 0; k < 4; k++) acc[i][j][k] = 0.0f;

    const int a_row_in = lane & 15;
    const int a_kseg   = (lane >> 4) << 4;
    const int b_row_in = (lane & 7) + ((lane >> 4) << 3);
    const int b_kseg   = ((lane >> 3) & 1) << 4;

    for (int ch = 0; ch < 12; ch++) {
        const size_t c0b = (size_t)ch * 128;
        #pragma unroll
        for (int r = 0; r < 4; r++) {
            int idx = tid + r * 256;
            int row = idx >> 3, seg = idx & 7;
            uint32_t so = sw128((uint32_t)(row * 128 + seg * 16));
            *(uint4*)(sA + so) = *(const uint4*)(Abase + (size_t)row * (KP * 2) + c0b + seg * 16);
            *(uint4*)(sB + so) = *(const uint4*)(Bbase + (size_t)row * (KP * 2) + c0b + seg * 16);
        }
        __syncthreads();

        #pragma unroll
        for (int kk = 0; kk < 4; kk++) {
            uint32_t af[4][4];
            #pragma unroll
            for (int mi = 0; mi < 4; mi++) {
                int row = warp_m * 64 + mi * 16 + a_row_in;
                uint32_t addr = sA_u + sw128((uint32_t)(row * 128 + kk * 32 + a_kseg));
                ldmatrix_x4(af[mi][0], af[mi][1], af[mi][2], af[mi][3], addr);
            }
            uint32_t bf[2][4];
            #pragma unroll
            for (int ni16 = 0; ni16 < 2; ni16++) {
                int row = warp_n * 32 + ni16 * 16 + b_row_in;
                uint32_t addr = sB_u + sw128((uint32_t)(row * 128 + kk * 32 + b_kseg));
                ldmatrix_x4(bf[ni16][0], bf[ni16][1], bf[ni16][2], bf[ni16][3], addr);
            }
            #pragma unroll
            for (int mi = 0; mi < 4; mi++)
                #pragma unroll
                for (int ni = 0; ni < 4; ni++) {
                    uint32_t b0 = bf[ni >> 1][(ni & 1) * 2 + 0];
                    uint32_t b1 = bf[ni >> 1][(ni & 1) * 2 + 1];
                    mma_bf16(acc[mi][ni][0], acc[mi][ni][1], acc[mi][ni][2], acc[mi][ni][3],
                             af[mi][0], af[mi][1], af[mi][2], af[mi][3], b0, b1);
                }
        }
        __syncthreads();
    }

    const int p0 = pt * 128 + warp_n * 32 + 2 * (lane & 3);
    #pragma unroll
    for (int mi = 0; mi < 4; mi++) {
        #pragma unroll
        for (int half = 0; half < 2; half++) {
            int m = mt * 128 + warp_m * 64 + mi * 16 + (lane >> 2) + half * 8;
            float bias;
            float* dst;
            if (m < 256)      { bias = bv[m];       dst = &g_v[((size_t)b * 256 + m) * HWS]; }
            else if (m < 288) { bias = bq[m - 256]; dst = &g_q[((size_t)b * 32 + (m - 256)) * HWS]; }
            else if (m < 320) { bias = bk[m - 288]; dst = &g_k[((size_t)b * 32 + (m - 288)) * HWS]; }
            else continue;
            #pragma unroll
            for (int ni = 0; ni < 4; ni++) {
                float2 v = make_float2(acc[mi][ni][half * 2 + 0] + bias,
                                       acc[mi][ni][half * 2 + 1] + bias);
                *(float2*)&dst[p0 + ni * 8] = v;
            }
        }
    }
}

// ---------------------------------------------------------------------------
// transpose: per channel-plane [H][W] -> [W][H] for q,k,v.
// plane id: 0..127 q, 128..255 k, 256..1279 v. 32x32 tiles, 256 threads.
// ---------------------------------------------------------------------------
__global__ void transpose_kernel()
{
    __shared__ float sm[32][33];
    const int plane = blockIdx.z;
    const float* src;
    float* dst;
    if (plane < 128)      { src = g_q + (size_t)plane * HWS;        dst = g_qT + (size_t)plane * HWS; }
    else if (plane < 256) { src = g_k + (size_t)(plane - 128) * HWS; dst = g_kT + (size_t)(plane - 128) * HWS; }
    else                  { src = g_v + (size_t)(plane - 256) * HWS; dst = g_vT + (size_t)(plane - 256) * HWS; }
    const int ti = blockIdx.y * 32, tj = blockIdx.x * 32;
    const int t = threadIdx.x;
    const int cc = t & 31, r0 = t >> 5;   // 8 rows per pass
    #pragma unroll
    for (int p = 0; p < 4; p++) {
        int r = r0 + p * 8;
        sm[r][cc] = src[(size_t)(ti + r) * WW + tj + cc];
    }
    __syncthreads();
    #pragma unroll
    for (int p = 0; p < 4; p++) {
        int r = r0 + p * 8;
        dst[(size_t)(tj + r) * HH + ti + cc] = sm[cc][r];
    }
}

// ---------------------------------------------------------------------------
// Fused criss-cross attention. Block (i, bh): phase 0 = row attention for row
// i (reads row-major planes), phase 1 = column attention for column i (reads
// transposed planes -> identical coalesced float4 loads). acc persists.
// ---------------------------------------------------------------------------
__global__ void attn_kernel(const float* __restrict__ x,
                            const float* __restrict__ gamma,
                            float* __restrict__ out)
{
    float* smem = (float*)smem_raw;
    float* E   = smem;               // 16384 floats, E[g*128 + j]
    float* Vs  = E + 16384;          // 8192, Vs[c*128 + g]
    float* Qs  = Vs + 8192;          // 1024
    float* Ks  = Qs + 1024;          // 1024
    float* red = Ks + 1024;          // 256

    const int i  = blockIdx.x;
    const int bh = blockIdx.y;
    const int b = bh >> 2, h = bh & 3;
    const int tid = threadIdx.x;
    const int j = tid & 127;
    const int half = tid >> 7;
    const int g0 = half * 64;
    const int cb = half * 32;

    float acc[32];
    #pragma unroll
    for (int c = 0; c < 32; c++) acc[c] = 0.0f;

    const size_t qk_base = ((size_t)b * 32 + h * 8) * HWS;
    const size_t v_base  = ((size_t)b * 256 + h * 64) * HWS;

    for (int phase = 0; phase < 2; phase++) {
        const float* Qp = phase ? g_qT : g_q;
        const float* Kp = phase ? g_kT : g_k;
        const float* Vp = phase ? g_vT : g_v;
        {
            int c = tid >> 5, w4 = tid & 31;
            size_t off = qk_base + ((size_t)c * HH + i) * WW + w4 * 4;
            *(float4*)&Qs[c * 128 + w4 * 4] = *(const float4*)&Qp[off];
            *(float4*)&Ks[c * 128 + w4 * 4] = *(const float4*)&Kp[off];
        }
        for (int idx = tid; idx < 2048; idx += 256) {
            int c = idx >> 5, w4 = idx & 31;
            *(float4*)&Vs[c * 128 + w4 * 4] =
                *(const float4*)&Vp[v_base + ((size_t)c * HH + i) * WW + w4 * 4];
        }
        __syncthreads();

        // energies: E[g][j] = sum_c Q[c][j] * K[c][g]
        float qr[8];
        #pragma unroll
        for (int c = 0; c < 8; c++) qr[c] = Qs[c * 128 + j];
        for (int g = g0; g < g0 + 64; g += 4) {
            float4 e = make_float4(0.f, 0.f, 0.f, 0.f);
            #pragma unroll
            for (int c = 0; c < 8; c++) {
                float4 kv = *(const float4*)&Ks[c * 128 + g];
                e.x += qr[c] * kv.x; e.y += qr[c] * kv.y;
                e.z += qr[c] * kv.z; e.w += qr[c] * kv.w;
            }
            E[(g + 0) * 128 + j] = e.x;
            E[(g + 1) * 128 + j] = e.y;
            E[(g + 2) * 128 + j] = e.z;
            E[(g + 3) * 128 + j] = e.w;
        }
        __syncthreads();

        // softmax over g (2 threads per j)
        float m = -1e30f;
        for (int g = g0; g < g0 + 64; g++) m = fmaxf(m, E[g * 128 + j]);
        red[tid] = m;
        __syncthreads();
        m = fmaxf(red[j], red[j + 128]);
        float s = 0.0f;
        for (int g = g0; g < g0 + 64; g++) {
            float p = __expf(E[g * 128 + j] - m);
            E[g * 128 + j] = p;
            s += p;
        }
        __syncthreads();
        red[tid] = s;
        __syncthreads();
        const float is = 1.0f / (red[j] + red[j + 128]);

        // O: acc[c] += sum_g (E[g][j]*is) * V[c][g]
        for (int g = 0; g < 128; g += 4) {
            float a0 = E[(g + 0) * 128 + j] * is;
            float a1 = E[(g + 1) * 128 + j] * is;
            float a2 = E[(g + 2) * 128 + j] * is;
            float a3 = E[(g + 3) * 128 + j] * is;
            #pragma unroll
            for (int c = 0; c < 32; c++) {
                const float4 v4 = *(const float4*)&Vs[(cb + c) * 128 + g];
                acc[c] += a0 * v4.x + a1 * v4.y + a2 * v4.z + a3 * v4.w;
            }
        }
        __syncthreads();
    }

    const float gm = gamma[0];
    #pragma unroll
    for (int c = 0; c < 32; c++) {
        size_t off = (((size_t)b * 256 + h * 64 + cb + c) * HH + i) * WW + j;
        out[off] = gm * acc[c] + x[off];
    }
}

// ---------------------------------------------------------------------------
extern "C" void kernel_launch(void* const* d_in, const int* in_sizes, int n_in,
                              void* d_out, int out_size)
{
    const float* x     = (const float*)d_in[0];
    const float* Wq    = (const float*)d_in[1];
    const float* bq    = (const float*)d_in[2];
    const float* Wk    = (const float*)d_in[3];
    const float* bk    = (const float*)d_in[4];
    const float* Wv    = (const float*)d_in[5];
    const float* bv    = (const float*)d_in[6];
    const float* gamma = (const float*)d_in[7];
    float* out = (float*)d_out;

    const int attn_smem = (16384 + 8192 + 1024 + 1024 + 256) * 4;  // 107,520
    cudaFuncSetAttribute(attn_kernel, cudaFuncAttributeMaxDynamicSharedMemorySize,
                         attn_smem);

    prep_w_kernel<<<384, 256>>>(Wq, Wk, Wv);
    prep_x_kernel<<<dim3(256, 4, NB), 256>>>(x);
    proj_mma_kernel<<<dim3(128, 3, NB), 256>>>(bq, bk, bv);
    transpose_kernel<<<dim3(4, 4, NB * 320), 256>>>();
    attn_kernel<<<dim3(HH, NB * 4), 256, attn_smem>>>(x, gamma, out);
}

// round 6
// speedup vs baseline: 2.2689x; 1.4630x over previous
#include <cuda_runtime.h>
#include <cuda_bf16.h>
#include <cuda_fp16.h>
#include <cstdint>

#define HH 128
#define WW 128
#define HWS 16384
#define NB 4
#define KP 768   // split-K: [Whi|Whi|Wlo] x [Xhi|Xlo|Xhi]

// ---------------- scratch (device globals; allocation-free rule) ------------
__device__ float g_q[(size_t)NB * 32 * HWS];
__device__ float g_k[(size_t)NB * 32 * HWS];
__device__ float g_v[(size_t)NB * 256 * HWS];
__device__ float g_qT[(size_t)NB * 32 * HWS];   // [b][c][W][H]
__device__ float g_kT[(size_t)NB * 32 * HWS];
__device__ float g_vT[(size_t)NB * 256 * HWS];
__device__ __align__(16) __nv_bfloat16 g_wsplit[(size_t)384 * KP];       // [m][k']
__device__ __align__(16) __nv_bfloat16 g_xt[(size_t)NB * HWS * KP];      // [b][p][k']

// single TU-wide dynamic smem symbol (char; cast per-kernel)
extern __shared__ __align__(1024) char smem_raw[];

static __device__ __forceinline__ uint32_t sw128(uint32_t off) {
    return off ^ ((off >> 3) & 0x70);
}
static __device__ __forceinline__ uint32_t sw256(uint32_t off) {
    return off ^ (((off >> 8) & 7) << 4);
}
static __device__ __forceinline__ uint32_t sw512(uint32_t off) {
    return off ^ (((off >> 9) & 7) << 4);
}
__device__ __forceinline__ uint32_t smem_u32(const void* p) {
    uint32_t a;
    asm("{ .reg .u64 t; cvta.to.shared.u64 t, %1; cvt.u32.u64 %0, t; }"
        : "=r"(a) : "l"(p));
    return a;
}
__device__ __forceinline__ void ldmatrix_x4(uint32_t& r0, uint32_t& r1,
                                            uint32_t& r2, uint32_t& r3, uint32_t addr) {
    asm volatile("ldmatrix.sync.aligned.m8n8.x4.shared.b16 {%0,%1,%2,%3}, [%4];"
                 : "=r"(r0), "=r"(r1), "=r"(r2), "=r"(r3) : "r"(addr));
}
__device__ __forceinline__ void mma_bf16(float& d0, float& d1, float& d2, float& d3,
                                         uint32_t a0, uint32_t a1, uint32_t a2, uint32_t a3,
                                         uint32_t b0, uint32_t b1) {
    asm volatile("mma.sync.aligned.m16n8k16.row.col.f32.bf16.bf16.f32 "
                 "{%0,%1,%2,%3}, {%4,%5,%6,%7}, {%8,%9}, {%0,%1,%2,%3};"
                 : "+f"(d0), "+f"(d1), "+f"(d2), "+f"(d3)
                 : "r"(a0), "r"(a1), "r"(a2), "r"(a3), "r"(b0), "r"(b1));
}
__device__ __forceinline__ void mma_f16(float& d0, float& d1, float& d2, float& d3,
                                        uint32_t a0, uint32_t a1, uint32_t a2, uint32_t a3,
                                        uint32_t b0, uint32_t b1) {
    asm volatile("mma.sync.aligned.m16n8k16.row.col.f32.f16.f16.f32 "
                 "{%0,%1,%2,%3}, {%4,%5,%6,%7}, {%8,%9}, {%0,%1,%2,%3};"
                 : "+f"(d0), "+f"(d1), "+f"(d2), "+f"(d3)
                 : "r"(a0), "r"(a1), "r"(a2), "r"(a3), "r"(b0), "r"(b1));
}

// ---------------------------------------------------------------------------
// prep_w: W' bf16 [384][768]; rows 0-255 Wv, 256-287 Wq, 288-319 Wk, 320-383 0
// ---------------------------------------------------------------------------
__global__ void prep_w_kernel(const float* __restrict__ Wq, const float* __restrict__ Wk,
                              const float* __restrict__ Wv)
{
    const int m = blockIdx.x;
    const int c = threadIdx.x;
    float w = 0.0f;
    if (m < 256)      w = Wv[m * 256 + c];
    else if (m < 288) w = Wq[(m - 256) * 256 + c];
    else if (m < 320) w = Wk[(m - 288) * 256 + c];
    __nv_bfloat16 hi = __float2bfloat16(w);
    __nv_bfloat16 lo = __float2bfloat16(w - __bfloat162float(hi));
    g_wsplit[(size_t)m * KP + c]       = hi;
    g_wsplit[(size_t)m * KP + 256 + c] = hi;
    g_wsplit[(size_t)m * KP + 512 + c] = lo;
}

// ---------------------------------------------------------------------------
// prep_x: XT' bf16 [b][p][768]
// ---------------------------------------------------------------------------
__global__ void prep_x_kernel(const float* __restrict__ x)
{
    __shared__ float sm[64][65];
    const int b = blockIdx.z, ct = blockIdx.y, pt = blockIdx.x;
    const int c0 = ct * 64, p0 = pt * 64;
    const int t = threadIdx.x;
    const int pj = t & 63, ci0 = t >> 6;
    const float* xb = x + ((size_t)b * 256 + c0) * HWS + p0;
    #pragma unroll
    for (int i = 0; i < 16; i++) {
        int ci = ci0 + i * 4;
        sm[ci][pj] = xb[(size_t)ci * HWS + pj];
    }
    __syncthreads();
    const int cp = t & 31, pl = t >> 5;
    #pragma unroll
    for (int i = 0; i < 8; i++) {
        int p = pl + i * 8;
        float f0 = sm[2 * cp][p], f1 = sm[2 * cp + 1][p];
        __nv_bfloat16 h0 = __float2bfloat16(f0), h1 = __float2bfloat16(f1);
        __nv_bfloat16 l0 = __float2bfloat16(f0 - __bfloat162float(h0));
        __nv_bfloat16 l1 = __float2bfloat16(f1 - __bfloat162float(h1));
        __nv_bfloat162 hp; hp.x = h0; hp.y = h1;
        __nv_bfloat162 lp; lp.x = l0; lp.y = l1;
        __nv_bfloat16* row = g_xt + ((size_t)b * HWS + p0 + p) * KP;
        *(__nv_bfloat162*)(row + c0 + 2 * cp)       = hp;
        *(__nv_bfloat162*)(row + 256 + c0 + 2 * cp) = lp;
        *(__nv_bfloat162*)(row + 512 + c0 + 2 * cp) = hp;
    }
}

// ---------------------------------------------------------------------------
// proj_mma (unchanged, known good)
// ---------------------------------------------------------------------------
__global__ void __launch_bounds__(256) proj_mma_kernel(
    const float* __restrict__ bq, const float* __restrict__ bk,
    const float* __restrict__ bv)
{
    __shared__ __align__(1024) char sA[128 * 128];
    __shared__ __align__(1024) char sB[128 * 128];

    const int tid = threadIdx.x;
    const int wid = tid >> 5, lane = tid & 31;
    const int warp_m = wid & 1;
    const int warp_n = wid >> 1;
    const int pt = blockIdx.x, mt = blockIdx.y, b = blockIdx.z;

    const char* Abase = (const char*)(g_wsplit + (size_t)mt * 128 * KP);
    const char* Bbase = (const char*)(g_xt + ((size_t)b * HWS + pt * 128) * KP);
    const uint32_t sA_u = smem_u32(sA);
    const uint32_t sB_u = smem_u32(sB);

    float acc[4][4][4];
    #pragma unroll
    for (int i = 0; i < 4; i++)
        #pragma unroll
        for (int j = 0; j < 4; j++)
            #pragma unroll
            for (int k = 0; k < 4; k++) acc[i][j][k] = 0.0f;

    const int a_row_in = lane & 15;
    const int a_kseg   = (lane >> 4) << 4;
    const int b_row_in = (lane & 7) + ((lane >> 4) << 3);
    const int b_kseg   = ((lane >> 3) & 1) << 4;

    for (int ch = 0; ch < 12; ch++) {
        const size_t c0b = (size_t)ch * 128;
        #pragma unroll
        for (int r = 0; r < 4; r++) {
            int idx = tid + r * 256;
            int row = idx >> 3, seg = idx & 7;
            uint32_t so = sw128((uint32_t)(row * 128 + seg * 16));
            *(uint4*)(sA + so) = *(const uint4*)(Abase + (size_t)row * (KP * 2) + c0b + seg * 16);
            *(uint4*)(sB + so) = *(const uint4*)(Bbase + (size_t)row * (KP * 2) + c0b + seg * 16);
        }
        __syncthreads();

        #pragma unroll
        for (int kk = 0; kk < 4; kk++) {
            uint32_t af[4][4];
            #pragma unroll
            for (int mi = 0; mi < 4; mi++) {
                int row = warp_m * 64 + mi * 16 + a_row_in;
                uint32_t addr = sA_u + sw128((uint32_t)(row * 128 + kk * 32 + a_kseg));
                ldmatrix_x4(af[mi][0], af[mi][1], af[mi][2], af[mi][3], addr);
            }
            uint32_t bf[2][4];
            #pragma unroll
            for (int ni16 = 0; ni16 < 2; ni16++) {
                int row = warp_n * 32 + ni16 * 16 + b_row_in;
                uint32_t addr = sB_u + sw128((uint32_t)(row * 128 + kk * 32 + b_kseg));
                ldmatrix_x4(bf[ni16][0], bf[ni16][1], bf[ni16][2], bf[ni16][3], addr);
            }
            #pragma unroll
            for (int mi = 0; mi < 4; mi++)
                #pragma unroll
                for (int ni = 0; ni < 4; ni++) {
                    uint32_t b0 = bf[ni >> 1][(ni & 1) * 2 + 0];
                    uint32_t b1 = bf[ni >> 1][(ni & 1) * 2 + 1];
                    mma_bf16(acc[mi][ni][0], acc[mi][ni][1], acc[mi][ni][2], acc[mi][ni][3],
                             af[mi][0], af[mi][1], af[mi][2], af[mi][3], b0, b1);
                }
        }
        __syncthreads();
    }

    const int p0 = pt * 128 + warp_n * 32 + 2 * (lane & 3);
    #pragma unroll
    for (int mi = 0; mi < 4; mi++) {
        #pragma unroll
        for (int half = 0; half < 2; half++) {
            int m = mt * 128 + warp_m * 64 + mi * 16 + (lane >> 2) + half * 8;
            float bias;
            float* dst;
            if (m < 256)      { bias = bv[m];       dst = &g_v[((size_t)b * 256 + m) * HWS]; }
            else if (m < 288) { bias = bq[m - 256]; dst = &g_q[((size_t)b * 32 + (m - 256)) * HWS]; }
            else if (m < 320) { bias = bk[m - 288]; dst = &g_k[((size_t)b * 32 + (m - 288)) * HWS]; }
            else continue;
            #pragma unroll
            for (int ni = 0; ni < 4; ni++) {
                float2 v = make_float2(acc[mi][ni][half * 2 + 0] + bias,
                                       acc[mi][ni][half * 2 + 1] + bias);
                *(float2*)&dst[p0 + ni * 8] = v;
            }
        }
    }
}

// ---------------------------------------------------------------------------
// transpose (unchanged)
// ---------------------------------------------------------------------------
__global__ void transpose_kernel()
{
    __shared__ float sm[32][33];
    const int plane = blockIdx.z;
    const float* src;
    float* dst;
    if (plane < 128)      { src = g_q + (size_t)plane * HWS;        dst = g_qT + (size_t)plane * HWS; }
    else if (plane < 256) { src = g_k + (size_t)(plane - 128) * HWS; dst = g_kT + (size_t)(plane - 128) * HWS; }
    else                  { src = g_v + (size_t)(plane - 256) * HWS; dst = g_vT + (size_t)(plane - 256) * HWS; }
    const int ti = blockIdx.y * 32, tj = blockIdx.x * 32;
    const int t = threadIdx.x;
    const int cc = t & 31, r0 = t >> 5;
    #pragma unroll
    for (int p = 0; p < 4; p++) {
        int r = r0 + p * 8;
        sm[r][cc] = src[(size_t)(ti + r) * WW + tj + cc];
    }
    __syncthreads();
    #pragma unroll
    for (int p = 0; p < 4; p++) {
        int r = r0 + p * 8;
        dst[(size_t)(tj + r) * HH + ti + cc] = sm[cc][r];
    }
}

// ---------------------------------------------------------------------------
// Tensor-core criss-cross attention.
// smem: [0,64K)   E fp32 [g][j] rows 512B sw512
//                 later overlaid: P fp16 [j][g] rows 256B sw256 in [0,32K)
//                                 Vhi fp16 [c][g] 256B rows in [32K,48K)
//                                 Vlo fp16 in [48K,64K)
//       [64K,80K) A op (K') bf16 [g][32 cols, 128B padded rows] sw128
//       [80K,96K) B op (Q') bf16 [j][...]
//       [96K,98K) red: 256 max + 256 sum floats
// ---------------------------------------------------------------------------
#define AT_E    0
#define AT_P    0
#define AT_VHI  32768
#define AT_VLO  49152
#define AT_A    65536
#define AT_B    81920
#define AT_RED  98304
#define AT_SMEM (98304 + 2048)

__global__ void __launch_bounds__(256, 2) attn_kernel(
    const float* __restrict__ x, const float* __restrict__ gamma,
    float* __restrict__ out)
{
    char* smem = smem_raw;
    float* redm = (float*)(smem + AT_RED);
    float* reds = redm + 256;

    const int i  = blockIdx.x;
    const int bh = blockIdx.y;
    const int b = bh >> 2, h = bh & 3;
    const int tid = threadIdx.x;
    const int wid = tid >> 5, lane = tid & 31;

    // ldmatrix lane addressing (same pattern as proj)
    const int a_row_in = lane & 15;
    const int a_kseg   = (lane >> 4) << 4;
    const int b_row_in = (lane & 7) + ((lane >> 4) << 3);
    const int b_kseg   = ((lane >> 3) & 1) << 4;

    // energy warp tiling: em = m-half (g), en = n-quarter (j)
    const int em = wid & 1, en = wid >> 1;

    const size_t qk_base = ((size_t)b * 32 + h * 8) * HWS;
    const size_t v_base  = ((size_t)b * 256 + h * 64) * HWS;

    float acc[4][2][4];          // O accumulators [mi][ni][4], persist phases
    #pragma unroll
    for (int mi = 0; mi < 4; mi++)
        #pragma unroll
        for (int ni = 0; ni < 2; ni++)
            #pragma unroll
            for (int k = 0; k < 4; k++) acc[mi][ni][k] = 0.0f;

    for (int phase = 0; phase < 2; phase++) {
        const float* Qp = phase ? g_qT : g_q;
        const float* Kp = phase ? g_kT : g_k;
        const float* Vp = phase ? g_vT : g_v;

        // ---- build energy operands: A = K' [g][24+pad], B = Q' ----
        {
            const int g = tid & 127, hf = tid >> 7;
            #pragma unroll
            for (int cc = 0; cc < 4; cc++) {
                int c = hf * 4 + cc;
                size_t off = qk_base + (size_t)c * HWS + (size_t)i * WW + g;
                float kv = Kp[off], qv = Qp[off];
                __nv_bfloat16 khi = __float2bfloat16(kv);
                __nv_bfloat16 klo = __float2bfloat16(kv - __bfloat162float(khi));
                __nv_bfloat16 qhi = __float2bfloat16(qv);
                __nv_bfloat16 qlo = __float2bfloat16(qv - __bfloat162float(qhi));
                *(__nv_bfloat16*)(smem + AT_A + sw128((uint32_t)(g * 128 + c * 2)))        = khi;
                *(__nv_bfloat16*)(smem + AT_A + sw128((uint32_t)(g * 128 + (c + 8) * 2)))  = khi;
                *(__nv_bfloat16*)(smem + AT_A + sw128((uint32_t)(g * 128 + (c + 16) * 2))) = klo;
                *(__nv_bfloat16*)(smem + AT_B + sw128((uint32_t)(g * 128 + c * 2)))        = qhi;
                *(__nv_bfloat16*)(smem + AT_B + sw128((uint32_t)(g * 128 + (c + 8) * 2)))  = qlo;
                *(__nv_bfloat16*)(smem + AT_B + sw128((uint32_t)(g * 128 + (c + 16) * 2))) = qhi;
            }
            // zero pad cols 24..31 (bytes 48..63)
            uint32_t pad = sw128((uint32_t)(g * 128 + 48));
            if (hf == 0) *(uint4*)(smem + AT_A + pad) = make_uint4(0, 0, 0, 0);
            else         *(uint4*)(smem + AT_B + pad) = make_uint4(0, 0, 0, 0);
        }
        __syncthreads();

        // ---- energy mma: E[g][j], warp tile m64 x n32, k=32 ----
        {
            float ef[4][4][4];
            #pragma unroll
            for (int mi = 0; mi < 4; mi++)
                #pragma unroll
                for (int ni = 0; ni < 4; ni++)
                    #pragma unroll
                    for (int k = 0; k < 4; k++) ef[mi][ni][k] = 0.0f;

            const uint32_t sA_u = smem_u32(smem + AT_A);
            const uint32_t sB_u = smem_u32(smem + AT_B);
            #pragma unroll
            for (int ks = 0; ks < 2; ks++) {
                uint32_t af[4][4];
                #pragma unroll
                for (int mi = 0; mi < 4; mi++) {
                    int row = em * 64 + mi * 16 + a_row_in;
                    ldmatrix_x4(af[mi][0], af[mi][1], af[mi][2], af[mi][3],
                                sA_u + sw128((uint32_t)(row * 128 + ks * 32 + a_kseg)));
                }
                uint32_t bfr[2][4];
                #pragma unroll
                for (int n16 = 0; n16 < 2; n16++) {
                    int row = en * 32 + n16 * 16 + b_row_in;
                    ldmatrix_x4(bfr[n16][0], bfr[n16][1], bfr[n16][2], bfr[n16][3],
                                sB_u + sw128((uint32_t)(row * 128 + ks * 32 + b_kseg)));
                }
                #pragma unroll
                for (int mi = 0; mi < 4; mi++)
                    #pragma unroll
                    for (int ni = 0; ni < 4; ni++)
                        mma_bf16(ef[mi][ni][0], ef[mi][ni][1], ef[mi][ni][2], ef[mi][ni][3],
                                 af[mi][0], af[mi][1], af[mi][2], af[mi][3],
                                 bfr[ni >> 1][(ni & 1) * 2 + 0], bfr[ni >> 1][(ni & 1) * 2 + 1]);
            }
            // store E (fp32, [g][j] rows 512B, sw512)
            #pragma unroll
            for (int mi = 0; mi < 4; mi++)
                #pragma unroll
                for (int ni = 0; ni < 4; ni++)
                    #pragma unroll
                    for (int hf = 0; hf < 2; hf++) {
                        int g = em * 64 + mi * 16 + (lane >> 2) + hf * 8;
                        int j = en * 32 + ni * 8 + (lane & 3) * 2;
                        float2 v = make_float2(ef[mi][ni][hf * 2 + 0], ef[mi][ni][hf * 2 + 1]);
                        *(float2*)(smem + AT_E + sw512((uint32_t)(g * 512 + j * 4))) = v;
                    }
        }
        __syncthreads();

        // ---- softmax: max, exp -> staged half2, sum, P=exp*is ----
        {
            const int j = tid & 127, hf = tid >> 7;
            const int g0 = hf * 64;
            float mx = -1e30f;
            #pragma unroll 8
            for (int g = g0; g < g0 + 64; g++)
                mx = fmaxf(mx, *(const float*)(smem + AT_E + sw512((uint32_t)(g * 512 + j * 4))));
            redm[tid] = mx;
            __syncthreads();
            mx = fmaxf(redm[j], redm[j + 128]);

            uint32_t stage[32];
            float sum = 0.0f;
            #pragma unroll 8
            for (int gp = 0; gp < 32; gp++) {
                int g = g0 + gp * 2;
                float e0 = *(const float*)(smem + AT_E + sw512((uint32_t)(g * 512 + j * 4)));
                float e1 = *(const float*)(smem + AT_E + sw512((uint32_t)((g + 1) * 512 + j * 4)));
                float p0 = __expf(e0 - mx);
                float p1 = __expf(e1 - mx);
                sum += p0 + p1;
                __half2 hp = __floats2half2_rn(p0, p1);
                stage[gp] = *(uint32_t*)&hp;
            }
            reds[tid] = sum;
            __syncthreads();   // all E reads done; P/V regions now writable
            const float is = 1.0f / (reds[j] + reds[j + 128]);
            const __half2 is2 = __floats2half2_rn(is, is);
            #pragma unroll 8
            for (int gp = 0; gp < 32; gp++) {
                int g = g0 + gp * 2;
                __half2 hp = *(__half2*)&stage[gp];
                __half2 r = __hmul2(hp, is2);
                *(uint32_t*)(smem + AT_P + sw256((uint32_t)(j * 256 + g * 2))) = *(uint32_t*)&r;
            }
        }

        // ---- build V fp16 hi/lo (into E's upper half; safe after sums sync) ----
        for (int idx = tid; idx < 2048; idx += 256) {
            int c = idx >> 5, g4 = (idx & 31) * 4;
            float4 v = *(const float4*)&Vp[v_base + ((size_t)c * HWS) + (size_t)i * WW + g4];
            __half h0 = __float2half_rn(v.x), h1 = __float2half_rn(v.y);
            __half h2 = __float2half_rn(v.z), h3 = __float2half_rn(v.w);
            __half l0 = __float2half_rn(v.x - __half2float(h0));
            __half l1 = __float2half_rn(v.y - __half2float(h1));
            __half l2 = __float2half_rn(v.z - __half2float(h2));
            __half l3 = __float2half_rn(v.w - __half2float(h3));
            uint32_t base = (uint32_t)(c * 256 + g4 * 2);
            __half2 hp0; hp0.x = h0; hp0.y = h1;
            __half2 hp1; hp1.x = h2; hp1.y = h3;
            __half2 lp0; lp0.x = l0; lp0.y = l1;
            __half2 lp1; lp1.x = l2; lp1.y = l3;
            *(uint32_t*)(smem + AT_VHI + sw256(base))     = *(uint32_t*)&hp0;
            *(uint32_t*)(smem + AT_VHI + sw256(base + 4)) = *(uint32_t*)&hp1;
            *(uint32_t*)(smem + AT_VLO + sw256(base))     = *(uint32_t*)&lp0;
            *(uint32_t*)(smem + AT_VLO + sw256(base + 4)) = *(uint32_t*)&lp1;
        }
        __syncthreads();

        // ---- O mma: acc[c][j] += sum_g V[c][g] * P[j][g], 2 terms ----
        {
            const uint32_t sP_u = smem_u32(smem + AT_P);
            #pragma unroll
            for (int term = 0; term < 2; term++) {
                const uint32_t sV_u = smem_u32(smem + (term ? AT_VLO : AT_VHI));
                #pragma unroll
                for (int ks = 0; ks < 8; ks++) {
                    uint32_t kb = (uint32_t)(ks * 32);
                    uint32_t af[4][4];
                    #pragma unroll
                    for (int mi = 0; mi < 4; mi++) {
                        int row = mi * 16 + a_row_in;
                        ldmatrix_x4(af[mi][0], af[mi][1], af[mi][2], af[mi][3],
                                    sV_u + sw256((uint32_t)(row * 256) + kb + a_kseg));
                    }
                    uint32_t bfr[4];
                    {
                        int row = wid * 16 + b_row_in;
                        ldmatrix_x4(bfr[0], bfr[1], bfr[2], bfr[3],
                                    sP_u + sw256((uint32_t)(row * 256) + kb + b_kseg));
                    }
                    #pragma unroll
                    for (int mi = 0; mi < 4; mi++)
                        #pragma unroll
                        for (int ni = 0; ni < 2; ni++)
                            mma_f16(acc[mi][ni][0], acc[mi][ni][1], acc[mi][ni][2], acc[mi][ni][3],
                                    af[mi][0], af[mi][1], af[mi][2], af[mi][3],
                                    bfr[ni * 2 + 0], bfr[ni * 2 + 1]);
                }
            }
        }
        __syncthreads();   // protect E/P/V before next phase
    }

    // ---- epilogue: out = gamma * acc + x ----
    const float gm = gamma[0];
    #pragma unroll
    for (int mi = 0; mi < 4; mi++)
        #pragma unroll
        for (int ni = 0; ni < 2; ni++)
            #pragma unroll
            for (int hf = 0; hf < 2; hf++) {
                int c = mi * 16 + (lane >> 2) + hf * 8;
                int j = wid * 16 + ni * 8 + (lane & 3) * 2;
                size_t off = (((size_t)b * 256 + h * 64 + c) * HH + i) * WW + j;
                float2 xv = *(const float2*)&x[off];
                float2 o = make_float2(gm * acc[mi][ni][hf * 2 + 0] + xv.x,
                                       gm * acc[mi][ni][hf * 2 + 1] + xv.y);
                *(float2*)&out[off] = o;
            }
}

// ---------------------------------------------------------------------------
extern "C" void kernel_launch(void* const* d_in, const int* in_sizes, int n_in,
                              void* d_out, int out_size)
{
    const float* x     = (const float*)d_in[0];
    const float* Wq    = (const float*)d_in[1];
    const float* bq    = (const float*)d_in[2];
    const float* Wk    = (const float*)d_in[3];
    const float* bk    = (const float*)d_in[4];
    const float* Wv    = (const float*)d_in[5];
    const float* bv    = (const float*)d_in[6];
    const float* gamma = (const float*)d_in[7];
    float* out = (float*)d_out;

    cudaFuncSetAttribute(attn_kernel, cudaFuncAttributeMaxDynamicSharedMemorySize,
                         AT_SMEM);

    prep_w_kernel<<<384, 256>>>(Wq, Wk, Wv);
    prep_x_kernel<<<dim3(256, 4, NB), 256>>>(x);
    proj_mma_kernel<<<dim3(128, 3, NB), 256>>>(bq, bk, bv);
    transpose_kernel<<<dim3(4, 4, NB * 320), 256>>>();
    attn_kernel<<<dim3(HH, NB * 4), 256, AT_SMEM>>>(x, gamma, out);
}

// round 7
// speedup vs baseline: 3.0312x; 1.3360x over previous
#include <cuda_runtime.h>
#include <cuda_bf16.h>
#include <cuda_fp16.h>
#include <cstdint>

#define HH 128
#define WW 128
#define HWS 16384
#define NB 4
#define KP 768   // split-K: [Whi|Whi|Wlo] x [Xhi|Xlo|Xhi]

// ---------------- scratch (device globals; allocation-free rule) ------------
__device__ float g_q[(size_t)NB * 32 * HWS];
__device__ float g_k[(size_t)NB * 32 * HWS];
__device__ float g_v[(size_t)NB * 256 * HWS];
__device__ float g_qT[(size_t)NB * 32 * HWS];   // [b][c][W][H]
__device__ float g_kT[(size_t)NB * 32 * HWS];
__device__ float g_vT[(size_t)NB * 256 * HWS];
__device__ __align__(16) __nv_bfloat16 g_wsplit[(size_t)384 * KP];       // [m][k']
__device__ __align__(16) __nv_bfloat16 g_xt[(size_t)NB * HWS * KP];      // [b][p][k']

// single TU-wide dynamic smem symbol (char; cast per-kernel)
extern __shared__ __align__(1024) char smem_raw[];

static __device__ __forceinline__ uint32_t sw128(uint32_t off) {
    return off ^ ((off >> 3) & 0x70);
}
static __device__ __forceinline__ uint32_t sw256(uint32_t off) {
    return off ^ (((off >> 8) & 7) << 4);
}
__device__ __forceinline__ uint32_t smem_u32(const void* p) {
    uint32_t a;
    asm("{ .reg .u64 t; cvta.to.shared.u64 t, %1; cvt.u32.u64 %0, t; }"
        : "=r"(a) : "l"(p));
    return a;
}
__device__ __forceinline__ void ldmatrix_x4(uint32_t& r0, uint32_t& r1,
                                            uint32_t& r2, uint32_t& r3, uint32_t addr) {
    asm volatile("ldmatrix.sync.aligned.m8n8.x4.shared.b16 {%0,%1,%2,%3}, [%4];"
                 : "=r"(r0), "=r"(r1), "=r"(r2), "=r"(r3) : "r"(addr));
}
__device__ __forceinline__ void ldmatrix_x4_trans(uint32_t& r0, uint32_t& r1,
                                                  uint32_t& r2, uint32_t& r3, uint32_t addr) {
    asm volatile("ldmatrix.sync.aligned.m8n8.x4.trans.shared.b16 {%0,%1,%2,%3}, [%4];"
                 : "=r"(r0), "=r"(r1), "=r"(r2), "=r"(r3) : "r"(addr));
}
__device__ __forceinline__ void mma_bf16(float& d0, float& d1, float& d2, float& d3,
                                         uint32_t a0, uint32_t a1, uint32_t a2, uint32_t a3,
                                         uint32_t b0, uint32_t b1) {
    asm volatile("mma.sync.aligned.m16n8k16.row.col.f32.bf16.bf16.f32 "
                 "{%0,%1,%2,%3}, {%4,%5,%6,%7}, {%8,%9}, {%0,%1,%2,%3};"
                 : "+f"(d0), "+f"(d1), "+f"(d2), "+f"(d3)
                 : "r"(a0), "r"(a1), "r"(a2), "r"(a3), "r"(b0), "r"(b1));
}
__device__ __forceinline__ void mma_f16(float& d0, float& d1, float& d2, float& d3,
                                        uint32_t a0, uint32_t a1, uint32_t a2, uint32_t a3,
                                        uint32_t b0, uint32_t b1) {
    asm volatile("mma.sync.aligned.m16n8k16.row.col.f32.f16.f16.f32 "
                 "{%0,%1,%2,%3}, {%4,%5,%6,%7}, {%8,%9}, {%0,%1,%2,%3};"
                 : "+f"(d0), "+f"(d1), "+f"(d2), "+f"(d3)
                 : "r"(a0), "r"(a1), "r"(a2), "r"(a3), "r"(b0), "r"(b1));
}
#define CP_ASYNC16(dst, src) \
    asm volatile("cp.async.cg.shared.global [%0], [%1], 16;" :: "r"(dst), "l"(src))
#define CP_COMMIT() asm volatile("cp.async.commit_group;" ::: "memory")
#define CP_WAIT1()  asm volatile("cp.async.wait_group 1;" ::: "memory")

// ---------------------------------------------------------------------------
// prep_w: W' bf16 [384][768]; rows 0-255 Wv, 256-287 Wq, 288-319 Wk, 320-383 0
// ---------------------------------------------------------------------------
__global__ void prep_w_kernel(const float* __restrict__ Wq, const float* __restrict__ Wk,
                              const float* __restrict__ Wv)
{
    const int m = blockIdx.x;
    const int c = threadIdx.x;
    float w = 0.0f;
    if (m < 256)      w = Wv[m * 256 + c];
    else if (m < 288) w = Wq[(m - 256) * 256 + c];
    else if (m < 320) w = Wk[(m - 288) * 256 + c];
    __nv_bfloat16 hi = __float2bfloat16(w);
    __nv_bfloat16 lo = __float2bfloat16(w - __bfloat162float(hi));
    g_wsplit[(size_t)m * KP + c]       = hi;
    g_wsplit[(size_t)m * KP + 256 + c] = hi;
    g_wsplit[(size_t)m * KP + 512 + c] = lo;
}

// ---------------------------------------------------------------------------
// prep_x: XT' bf16 [b][p][768]
// ---------------------------------------------------------------------------
__global__ void prep_x_kernel(const float* __restrict__ x)
{
    __shared__ float sm[64][65];
    const int b = blockIdx.z, ct = blockIdx.y, pt = blockIdx.x;
    const int c0 = ct * 64, p0 = pt * 64;
    const int t = threadIdx.x;
    const int pj = t & 63, ci0 = t >> 6;
    const float* xb = x + ((size_t)b * 256 + c0) * HWS + p0;
    #pragma unroll
    for (int i = 0; i < 16; i++) {
        int ci = ci0 + i * 4;
        sm[ci][pj] = xb[(size_t)ci * HWS + pj];
    }
    __syncthreads();
    const int cp = t & 31, pl = t >> 5;
    #pragma unroll
    for (int i = 0; i < 8; i++) {
        int p = pl + i * 8;
        float f0 = sm[2 * cp][p], f1 = sm[2 * cp + 1][p];
        __nv_bfloat16 h0 = __float2bfloat16(f0), h1 = __float2bfloat16(f1);
        __nv_bfloat16 l0 = __float2bfloat16(f0 - __bfloat162float(h0));
        __nv_bfloat16 l1 = __float2bfloat16(f1 - __bfloat162float(h1));
        __nv_bfloat162 hp; hp.x = h0; hp.y = h1;
        __nv_bfloat162 lp; lp.x = l0; lp.y = l1;
        __nv_bfloat16* row = g_xt + ((size_t)b * HWS + p0 + p) * KP;
        *(__nv_bfloat162*)(row + c0 + 2 * cp)       = hp;
        *(__nv_bfloat162*)(row + 256 + c0 + 2 * cp) = lp;
        *(__nv_bfloat162*)(row + 512 + c0 + 2 * cp) = hp;
    }
}

// ---------------------------------------------------------------------------
// proj_mma: 2-stage cp.async double-buffered bf16 mma GEMM.
// dyn smem: stage s at s*32768: A [0,16K), B [16K,32K)
// ---------------------------------------------------------------------------
__global__ void __launch_bounds__(256) proj_mma_kernel(
    const float* __restrict__ bq, const float* __restrict__ bk,
    const float* __restrict__ bv)
{
    char* smem = smem_raw;
    const uint32_t smem_base = smem_u32(smem);
    const int tid = threadIdx.x;
    const int wid = tid >> 5, lane = tid & 31;
    const int warp_m = wid & 1;
    const int warp_n = wid >> 1;
    const int pt = blockIdx.x, mt = blockIdx.y, b = blockIdx.z;

    const char* Abase = (const char*)(g_wsplit + (size_t)mt * 128 * KP);
    const char* Bbase = (const char*)(g_xt + ((size_t)b * HWS + pt * 128) * KP);

    float acc[4][4][4];
    #pragma unroll
    for (int i = 0; i < 4; i++)
        #pragma unroll
        for (int j = 0; j < 4; j++)
            #pragma unroll
            for (int k = 0; k < 4; k++) acc[i][j][k] = 0.0f;

    const int a_row_in = lane & 15;
    const int a_kseg   = (lane >> 4) << 4;
    const int b_row_in = (lane & 7) + ((lane >> 4) << 3);
    const int b_kseg   = ((lane >> 3) & 1) << 4;

    const int ld_row = tid >> 3, ld_seg = tid & 7;   // per-thread load slot

    // issue chunk ch into stage st
    auto issue = [&](int ch, int st) {
        const size_t c0b = (size_t)ch * 128;
        const uint32_t sb = smem_base + st * 32768;
        #pragma unroll
        for (int r = 0; r < 4; r++) {
            int row = ld_row + r * 32;
            uint32_t so = sw128((uint32_t)(row * 128 + ld_seg * 16));
            CP_ASYNC16(sb + so,         Abase + (size_t)row * (KP * 2) + c0b + ld_seg * 16);
            CP_ASYNC16(sb + 16384 + so, Bbase + (size_t)row * (KP * 2) + c0b + ld_seg * 16);
        }
    };

    issue(0, 0);
    CP_COMMIT();

    for (int ch = 0; ch < 12; ch++) {
        const int st = ch & 1;
        if (ch + 1 < 12) issue(ch + 1, st ^ 1);
        CP_COMMIT();
        CP_WAIT1();
        __syncthreads();

        const uint32_t sA_u = smem_base + st * 32768;
        const uint32_t sB_u = sA_u + 16384;
        #pragma unroll
        for (int kk = 0; kk < 4; kk++) {
            uint32_t af[4][4];
            #pragma unroll
            for (int mi = 0; mi < 4; mi++) {
                int row = warp_m * 64 + mi * 16 + a_row_in;
                ldmatrix_x4(af[mi][0], af[mi][1], af[mi][2], af[mi][3],
                            sA_u + sw128((uint32_t)(row * 128 + kk * 32 + a_kseg)));
            }
            uint32_t bf[2][4];
            #pragma unroll
            for (int ni16 = 0; ni16 < 2; ni16++) {
                int row = warp_n * 32 + ni16 * 16 + b_row_in;
                ldmatrix_x4(bf[ni16][0], bf[ni16][1], bf[ni16][2], bf[ni16][3],
                            sB_u + sw128((uint32_t)(row * 128 + kk * 32 + b_kseg)));
            }
            #pragma unroll
            for (int mi = 0; mi < 4; mi++)
                #pragma unroll
                for (int ni = 0; ni < 4; ni++)
                    mma_bf16(acc[mi][ni][0], acc[mi][ni][1], acc[mi][ni][2], acc[mi][ni][3],
                             af[mi][0], af[mi][1], af[mi][2], af[mi][3],
                             bf[ni >> 1][(ni & 1) * 2 + 0], bf[ni >> 1][(ni & 1) * 2 + 1]);
        }
        __syncthreads();
    }

    const int p0 = pt * 128 + warp_n * 32 + 2 * (lane & 3);
    #pragma unroll
    for (int mi = 0; mi < 4; mi++) {
        #pragma unroll
        for (int half = 0; half < 2; half++) {
            int m = mt * 128 + warp_m * 64 + mi * 16 + (lane >> 2) + half * 8;
            float bias;
            float* dst;
            if (m < 256)      { bias = bv[m];       dst = &g_v[((size_t)b * 256 + m) * HWS]; }
            else if (m < 288) { bias = bq[m - 256]; dst = &g_q[((size_t)b * 32 + (m - 256)) * HWS]; }
            else if (m < 320) { bias = bk[m - 288]; dst = &g_k[((size_t)b * 32 + (m - 288)) * HWS]; }
            else continue;
            #pragma unroll
            for (int ni = 0; ni < 4; ni++) {
                float2 v = make_float2(acc[mi][ni][half * 2 + 0] + bias,
                                       acc[mi][ni][half * 2 + 1] + bias);
                *(float2*)&dst[p0 + ni * 8] = v;
            }
        }
    }
}

// ---------------------------------------------------------------------------
// transpose (unchanged)
// ---------------------------------------------------------------------------
__global__ void transpose_kernel()
{
    __shared__ float sm[32][33];
    const int plane = blockIdx.z;
    const float* src;
    float* dst;
    if (plane < 128)      { src = g_q + (size_t)plane * HWS;        dst = g_qT + (size_t)plane * HWS; }
    else if (plane < 256) { src = g_k + (size_t)(plane - 128) * HWS; dst = g_kT + (size_t)(plane - 128) * HWS; }
    else                  { src = g_v + (size_t)(plane - 256) * HWS; dst = g_vT + (size_t)(plane - 256) * HWS; }
    const int ti = blockIdx.y * 32, tj = blockIdx.x * 32;
    const int t = threadIdx.x;
    const int cc = t & 31, r0 = t >> 5;
    #pragma unroll
    for (int p = 0; p < 4; p++) {
        int r = r0 + p * 8;
        sm[r][cc] = src[(size_t)(ti + r) * WW + tj + cc];
    }
    __syncthreads();
    #pragma unroll
    for (int p = 0; p < 4; p++) {
        int r = r0 + p * 8;
        dst[(size_t)(tj + r) * HH + ti + cc] = sm[cc][r];
    }
}

// ---------------------------------------------------------------------------
// Tensor-core criss-cross attention, register-resident softmax (no max pass).
// smem: [0,32K)   P fp16 [g][j], 256B rows, sw256
//       [32K,48K) Vhi fp16 [c][g] 256B rows sw256
//       [48K,64K) Vlo
//       [64K,80K) A op (K') bf16 [g][24+pad] 128B rows sw128
//       [80K,96K) B op (Q')
//       [96K,97K) ssum[2][128] fp32
// ---------------------------------------------------------------------------
#define AT_P    0
#define AT_VHI  32768
#define AT_VLO  49152
#define AT_A    65536
#define AT_B    81920
#define AT_SSUM 98304
#define AT_SMEM (98304 + 1024)

__global__ void __launch_bounds__(256, 2) attn_kernel(
    const float* __restrict__ x, const float* __restrict__ gamma,
    float* __restrict__ out)
{
    char* smem = smem_raw;
    float* ssum = (float*)(smem + AT_SSUM);   // ssum[em*128 + j]

    const int i  = blockIdx.x;
    const int bh = blockIdx.y;
    const int b = bh >> 2, h = bh & 3;
    const int tid = threadIdx.x;
    const int wid = tid >> 5, lane = tid & 31;

    const int a_row_in = lane & 15;
    const int a_kseg   = (lane >> 4) << 4;
    const int b_row_in = (lane & 7) + ((lane >> 4) << 3);
    const int b_kseg   = ((lane >> 3) & 1) << 4;

    const int em = wid & 1, en = wid >> 1;    // energy warp tiling

    const size_t qk_base = ((size_t)b * 32 + h * 8) * HWS;
    const size_t v_base  = ((size_t)b * 256 + h * 64) * HWS;

    float acc[8][4];                          // O acc [ni(c8)][4], m=j per warp
    #pragma unroll
    for (int ni = 0; ni < 8; ni++)
        #pragma unroll
        for (int k = 0; k < 4; k++) acc[ni][k] = 0.0f;

    for (int phase = 0; phase < 2; phase++) {
        const float* Qp = phase ? g_qT : g_q;
        const float* Kp = phase ? g_kT : g_k;
        const float* Vp = phase ? g_vT : g_v;

        // ---- build energy operands A=K', B=Q' (bf16 3-term split) ----
        {
            const int g = tid & 127, hf = tid >> 7;
            #pragma unroll
            for (int cc = 0; cc < 4; cc++) {
                int c = hf * 4 + cc;
                size_t off = qk_base + (size_t)c * HWS + (size_t)i * WW + g;
                float kv = Kp[off], qv = Qp[off];
                __nv_bfloat16 khi = __float2bfloat16(kv);
                __nv_bfloat16 klo = __float2bfloat16(kv - __bfloat162float(khi));
                __nv_bfloat16 qhi = __float2bfloat16(qv);
                __nv_bfloat16 qlo = __float2bfloat16(qv - __bfloat162float(qhi));
                *(__nv_bfloat16*)(smem + AT_A + sw128((uint32_t)(g * 128 + c * 2)))        = khi;
                *(__nv_bfloat16*)(smem + AT_A + sw128((uint32_t)(g * 128 + (c + 8) * 2)))  = khi;
                *(__nv_bfloat16*)(smem + AT_A + sw128((uint32_t)(g * 128 + (c + 16) * 2))) = klo;
                *(__nv_bfloat16*)(smem + AT_B + sw128((uint32_t)(g * 128 + c * 2)))        = qhi;
                *(__nv_bfloat16*)(smem + AT_B + sw128((uint32_t)(g * 128 + (c + 8) * 2)))  = qlo;
                *(__nv_bfloat16*)(smem + AT_B + sw128((uint32_t)(g * 128 + (c + 16) * 2))) = qhi;
            }
            uint32_t pad = sw128((uint32_t)(g * 128 + 48));
            if (hf == 0) *(uint4*)(smem + AT_A + pad) = make_uint4(0, 0, 0, 0);
            else         *(uint4*)(smem + AT_B + pad) = make_uint4(0, 0, 0, 0);
        }
        // ---- build V fp16 hi/lo [c][g] ----
        for (int idx = tid; idx < 2048; idx += 256) {
            int c = idx >> 5, g4 = (idx & 31) * 4;
            float4 v = *(const float4*)&Vp[v_base + (size_t)c * HWS + (size_t)i * WW + g4];
            __half h0 = __float2half_rn(v.x), h1 = __float2half_rn(v.y);
            __half h2 = __float2half_rn(v.z), h3 = __float2half_rn(v.w);
            __half l0 = __float2half_rn(v.x - __half2float(h0));
            __half l1 = __float2half_rn(v.y - __half2float(h1));
            __half l2 = __float2half_rn(v.z - __half2float(h2));
            __half l3 = __float2half_rn(v.w - __half2float(h3));
            uint32_t base = (uint32_t)(c * 256 + g4 * 2);
            __half2 hp0; hp0.x = h0; hp0.y = h1;
            __half2 hp1; hp1.x = h2; hp1.y = h3;
            __half2 lp0; lp0.x = l0; lp0.y = l1;
            __half2 lp1; lp1.x = l2; lp1.y = l3;
            *(uint32_t*)(smem + AT_VHI + sw256(base))     = *(uint32_t*)&hp0;
            *(uint32_t*)(smem + AT_VHI + sw256(base + 4)) = *(uint32_t*)&hp1;
            *(uint32_t*)(smem + AT_VLO + sw256(base))     = *(uint32_t*)&lp0;
            *(uint32_t*)(smem + AT_VLO + sw256(base + 4)) = *(uint32_t*)&lp1;
        }
        __syncthreads();

        // ---- energy mma: ef[mi][ni][k]; g = em*64+mi*16+.., j = en*32+ni*8+.. ----
        float ef[4][4][4];
        #pragma unroll
        for (int mi = 0; mi < 4; mi++)
            #pragma unroll
            for (int ni = 0; ni < 4; ni++)
                #pragma unroll
                for (int k = 0; k < 4; k++) ef[mi][ni][k] = 0.0f;
        {
            const uint32_t sA_u = smem_u32(smem + AT_A);
            const uint32_t sB_u = smem_u32(smem + AT_B);
            #pragma unroll
            for (int ks = 0; ks < 2; ks++) {
                uint32_t af[4][4];
                #pragma unroll
                for (int mi = 0; mi < 4; mi++) {
                    int row = em * 64 + mi * 16 + a_row_in;
                    ldmatrix_x4(af[mi][0], af[mi][1], af[mi][2], af[mi][3],
                                sA_u + sw128((uint32_t)(row * 128 + ks * 32 + a_kseg)));
                }
                uint32_t bfr[2][4];
                #pragma unroll
                for (int n16 = 0; n16 < 2; n16++) {
                    int row = en * 32 + n16 * 16 + b_row_in;
                    ldmatrix_x4(bfr[n16][0], bfr[n16][1], bfr[n16][2], bfr[n16][3],
                                sB_u + sw128((uint32_t)(row * 128 + ks * 32 + b_kseg)));
                }
                #pragma unroll
                for (int mi = 0; mi < 4; mi++)
                    #pragma unroll
                    for (int ni = 0; ni < 4; ni++)
                        mma_bf16(ef[mi][ni][0], ef[mi][ni][1], ef[mi][ni][2], ef[mi][ni][3],
                                 af[mi][0], af[mi][1], af[mi][2], af[mi][3],
                                 bfr[ni >> 1][(ni & 1) * 2 + 0], bfr[ni >> 1][(ni & 1) * 2 + 1]);
            }
        }

        // ---- exp in registers + per-j column sums (no max pass) ----
        float psum[4][2];
        #pragma unroll
        for (int ni = 0; ni < 4; ni++) { psum[ni][0] = 0.0f; psum[ni][1] = 0.0f; }
        #pragma unroll
        for (int mi = 0; mi < 4; mi++)
            #pragma unroll
            for (int ni = 0; ni < 4; ni++) {
                ef[mi][ni][0] = __expf(ef[mi][ni][0]);
                ef[mi][ni][1] = __expf(ef[mi][ni][1]);
                ef[mi][ni][2] = __expf(ef[mi][ni][2]);
                ef[mi][ni][3] = __expf(ef[mi][ni][3]);
                psum[ni][0] += ef[mi][ni][0] + ef[mi][ni][2];
                psum[ni][1] += ef[mi][ni][1] + ef[mi][ni][3];
            }
        #pragma unroll
        for (int ni = 0; ni < 4; ni++) {
            #pragma unroll
            for (int d = 4; d <= 16; d <<= 1) {
                psum[ni][0] += __shfl_xor_sync(0xffffffffu, psum[ni][0], d);
                psum[ni][1] += __shfl_xor_sync(0xffffffffu, psum[ni][1], d);
            }
        }
        if ((lane >> 2) == 0) {
            #pragma unroll
            for (int ni = 0; ni < 4; ni++) {
                int j0 = en * 32 + ni * 8 + (lane & 3) * 2;
                *(float2*)&ssum[em * 128 + j0] = make_float2(psum[ni][0], psum[ni][1]);
            }
        }
        __syncthreads();

        // ---- normalize + store P fp16 [g][j] ----
        #pragma unroll
        for (int ni = 0; ni < 4; ni++) {
            int j0 = en * 32 + ni * 8 + (lane & 3) * 2;
            float2 sa = *(float2*)&ssum[j0];
            float2 sb = *(float2*)&ssum[128 + j0];
            float is0 = 1.0f / (sa.x + sb.x);
            float is1 = 1.0f / (sa.y + sb.y);
            #pragma unroll
            for (int mi = 0; mi < 4; mi++) {
                int g0 = em * 64 + mi * 16 + (lane >> 2);
                __half2 p0 = __floats2half2_rn(ef[mi][ni][0] * is0, ef[mi][ni][1] * is1);
                __half2 p1 = __floats2half2_rn(ef[mi][ni][2] * is0, ef[mi][ni][3] * is1);
                *(uint32_t*)(smem + AT_P + sw256((uint32_t)(g0 * 256 + j0 * 2)))       = *(uint32_t*)&p0;
                *(uint32_t*)(smem + AT_P + sw256((uint32_t)((g0 + 8) * 256 + j0 * 2))) = *(uint32_t*)&p1;
            }
        }
        __syncthreads();

        // ---- O mma: A = P (m=j, k=g, trans-load), B = V (n=c, k=g) ----
        {
            const uint32_t sP_u = smem_u32(smem + AT_P);
            const int p_row_in = (lane & 7) + (((lane >> 4) & 1) << 3);
            const int p_col    = (wid << 4) + (((lane >> 3) & 1) << 3);
            #pragma unroll
            for (int term = 0; term < 2; term++) {
                const uint32_t sV_u = smem_u32(smem + (term ? AT_VLO : AT_VHI));
                #pragma unroll
                for (int ks = 0; ks < 8; ks++) {
                    uint32_t af[4];
                    {
                        int row = ks * 16 + p_row_in;
                        ldmatrix_x4_trans(af[0], af[1], af[2], af[3],
                                          sP_u + sw256((uint32_t)(row * 256 + p_col * 2)));
                    }
                    uint32_t bfr[4][4];
                    #pragma unroll
                    for (int n16 = 0; n16 < 4; n16++) {
                        int row = n16 * 16 + b_row_in;
                        ldmatrix_x4(bfr[n16][0], bfr[n16][1], bfr[n16][2], bfr[n16][3],
                                    sV_u + sw256((uint32_t)(row * 256 + ks * 32) + (uint32_t)b_kseg));
                    }
                    #pragma unroll
                    for (int n16 = 0; n16 < 4; n16++)
                        #pragma unroll
                        for (int sub = 0; sub < 2; sub++)
                            mma_f16(acc[n16 * 2 + sub][0], acc[n16 * 2 + sub][1],
                                    acc[n16 * 2 + sub][2], acc[n16 * 2 + sub][3],
                                    af[0], af[1], af[2], af[3],
                                    bfr[n16][sub * 2 + 0], bfr[n16][sub * 2 + 1]);
                }
            }
        }
        __syncthreads();   // protect A/B/V/P before next phase
    }

    // ---- epilogue: acc[ni][k]: j = wid*16 + (lane>>2) + (k>=2)*8, c = ni*8 + (lane&3)*2 + (k&1)
    const float gm = gamma[0];
    const size_t bch = (size_t)b * 256 + h * 64;
    const int jb = wid * 16 + (lane >> 2);
    #pragma unroll
    for (int ni = 0; ni < 8; ni++) {
        int c0 = ni * 8 + (lane & 3) * 2;
        #pragma unroll
        for (int hf = 0; hf < 2; hf++) {
            int j = jb + hf * 8;
            size_t off0 = ((bch + c0) * HH + i) * WW + j;
            size_t off1 = off0 + HWS;   // c0+1
            out[off0] = gm * acc[ni][hf * 2 + 0] + x[off0];
            out[off1] = gm * acc[ni][hf * 2 + 1] + x[off1];
        }
    }
}

// ---------------------------------------------------------------------------
extern "C" void kernel_launch(void* const* d_in, const int* in_sizes, int n_in,
                              void* d_out, int out_size)
{
    const float* x     = (const float*)d_in[0];
    const float* Wq    = (const float*)d_in[1];
    const float* bq    = (const float*)d_in[2];
    const float* Wk    = (const float*)d_in[3];
    const float* bk    = (const float*)d_in[4];
    const float* Wv    = (const float*)d_in[5];
    const float* bv    = (const float*)d_in[6];
    const float* gamma = (const float*)d_in[7];
    float* out = (float*)d_out;

    cudaFuncSetAttribute(attn_kernel, cudaFuncAttributeMaxDynamicSharedMemorySize,
                         AT_SMEM);
    cudaFuncSetAttribute(proj_mma_kernel, cudaFuncAttributeMaxDynamicSharedMemorySize,
                         65536);

    prep_w_kernel<<<384, 256>>>(Wq, Wk, Wv);
    prep_x_kernel<<<dim3(256, 4, NB), 256>>>(x);
    proj_mma_kernel<<<dim3(128, 3, NB), 256, 65536>>>(bq, bk, bv);
    transpose_kernel<<<dim3(4, 4, NB * 320), 256>>>();
    attn_kernel<<<dim3(HH, NB * 4), 256, AT_SMEM>>>(x, gamma, out);
}

// round 8
// speedup vs baseline: 3.2461x; 1.0709x over previous
#include <cuda_runtime.h>
#include <cuda_bf16.h>
#include <cuda_fp16.h>
#include <cstdint>

#define HH 128
#define WW 128
#define HWS 16384
#define NB 4
#define KP 512   // split-K storage: [hi(256) | lo(256)]; 12 virtual chunks at GEMM

// ---------------- scratch (device globals; allocation-free rule) ------------
__device__ float g_q[(size_t)NB * 32 * HWS];
__device__ float g_k[(size_t)NB * 32 * HWS];
__device__ float g_v[(size_t)NB * 256 * HWS];
__device__ float g_qT[(size_t)NB * 32 * HWS];   // [b][c][W][H]
__device__ float g_kT[(size_t)NB * 32 * HWS];
__device__ float g_vT[(size_t)NB * 256 * HWS];
__device__ __align__(16) __nv_bfloat16 g_wsplit[(size_t)384 * KP];       // [m][hi|lo]
__device__ __align__(16) __nv_bfloat16 g_xt[(size_t)NB * HWS * KP];      // [b][p][hi|lo]

// single TU-wide dynamic smem symbol (char; cast per-kernel)
extern __shared__ __align__(1024) char smem_raw[];

static __device__ __forceinline__ uint32_t sw128(uint32_t off) {
    return off ^ ((off >> 3) & 0x70);
}
static __device__ __forceinline__ uint32_t sw256(uint32_t off) {
    return off ^ (((off >> 8) & 7) << 4);
}
__device__ __forceinline__ uint32_t smem_u32(const void* p) {
    uint32_t a;
    asm("{ .reg .u64 t; cvta.to.shared.u64 t, %1; cvt.u32.u64 %0, t; }"
        : "=r"(a) : "l"(p));
    return a;
}
__device__ __forceinline__ void ldmatrix_x4(uint32_t& r0, uint32_t& r1,
                                            uint32_t& r2, uint32_t& r3, uint32_t addr) {
    asm volatile("ldmatrix.sync.aligned.m8n8.x4.shared.b16 {%0,%1,%2,%3}, [%4];"
                 : "=r"(r0), "=r"(r1), "=r"(r2), "=r"(r3) : "r"(addr));
}
__device__ __forceinline__ void ldmatrix_x4_trans(uint32_t& r0, uint32_t& r1,
                                                  uint32_t& r2, uint32_t& r3, uint32_t addr) {
    asm volatile("ldmatrix.sync.aligned.m8n8.x4.trans.shared.b16 {%0,%1,%2,%3}, [%4];"
                 : "=r"(r0), "=r"(r1), "=r"(r2), "=r"(r3) : "r"(addr));
}
__device__ __forceinline__ void mma_bf16(float& d0, float& d1, float& d2, float& d3,
                                         uint32_t a0, uint32_t a1, uint32_t a2, uint32_t a3,
                                         uint32_t b0, uint32_t b1) {
    asm volatile("mma.sync.aligned.m16n8k16.row.col.f32.bf16.bf16.f32 "
                 "{%0,%1,%2,%3}, {%4,%5,%6,%7}, {%8,%9}, {%0,%1,%2,%3};"
                 : "+f"(d0), "+f"(d1), "+f"(d2), "+f"(d3)
                 : "r"(a0), "r"(a1), "r"(a2), "r"(a3), "r"(b0), "r"(b1));
}
__device__ __forceinline__ void mma_f16(float& d0, float& d1, float& d2, float& d3,
                                        uint32_t a0, uint32_t a1, uint32_t a2, uint32_t a3,
                                        uint32_t b0, uint32_t b1) {
    asm volatile("mma.sync.aligned.m16n8k16.row.col.f32.f16.f16.f32 "
                 "{%0,%1,%2,%3}, {%4,%5,%6,%7}, {%8,%9}, {%0,%1,%2,%3};"
                 : "+f"(d0), "+f"(d1), "+f"(d2), "+f"(d3)
                 : "r"(a0), "r"(a1), "r"(a2), "r"(a3), "r"(b0), "r"(b1));
}
#define CP_ASYNC16(dst, src) \
    asm volatile("cp.async.cg.shared.global [%0], [%1], 16;" :: "r"(dst), "l"(src))
#define CP_COMMIT() asm volatile("cp.async.commit_group;" ::: "memory")
#define CP_WAIT1()  asm volatile("cp.async.wait_group 1;" ::: "memory")

// ---------------------------------------------------------------------------
// prep_w: W' bf16 [384][512]; rows 0-255 Wv, 256-287 Wq, 288-319 Wk, 320-383 0
// cols [0:256)=hi, [256:512)=lo
// ---------------------------------------------------------------------------
__global__ void prep_w_kernel(const float* __restrict__ Wq, const float* __restrict__ Wk,
                              const float* __restrict__ Wv)
{
    const int m = blockIdx.x;
    const int c = threadIdx.x;
    float w = 0.0f;
    if (m < 256)      w = Wv[m * 256 + c];
    else if (m < 288) w = Wq[(m - 256) * 256 + c];
    else if (m < 320) w = Wk[(m - 288) * 256 + c];
    __nv_bfloat16 hi = __float2bfloat16(w);
    __nv_bfloat16 lo = __float2bfloat16(w - __bfloat162float(hi));
    g_wsplit[(size_t)m * KP + c]       = hi;
    g_wsplit[(size_t)m * KP + 256 + c] = lo;
}

// ---------------------------------------------------------------------------
// prep_x: XT' bf16 [b][p][512]: cols [0:256)=hi, [256:512)=lo
// ---------------------------------------------------------------------------
__global__ void prep_x_kernel(const float* __restrict__ x)
{
    __shared__ float sm[64][65];
    const int b = blockIdx.z, ct = blockIdx.y, pt = blockIdx.x;
    const int c0 = ct * 64, p0 = pt * 64;
    const int t = threadIdx.x;
    const int pj = t & 63, ci0 = t >> 6;
    const float* xb = x + ((size_t)b * 256 + c0) * HWS + p0;
    #pragma unroll
    for (int i = 0; i < 16; i++) {
        int ci = ci0 + i * 4;
        sm[ci][pj] = xb[(size_t)ci * HWS + pj];
    }
    __syncthreads();
    const int cp = t & 31, pl = t >> 5;
    #pragma unroll
    for (int i = 0; i < 8; i++) {
        int p = pl + i * 8;
        float f0 = sm[2 * cp][p], f1 = sm[2 * cp + 1][p];
        __nv_bfloat16 h0 = __float2bfloat16(f0), h1 = __float2bfloat16(f1);
        __nv_bfloat16 l0 = __float2bfloat16(f0 - __bfloat162float(h0));
        __nv_bfloat16 l1 = __float2bfloat16(f1 - __bfloat162float(h1));
        __nv_bfloat162 hp; hp.x = h0; hp.y = h1;
        __nv_bfloat162 lp; lp.x = l0; lp.y = l1;
        __nv_bfloat16* row = g_xt + ((size_t)b * HWS + p0 + p) * KP;
        *(__nv_bfloat162*)(row + c0 + 2 * cp)       = hp;
        *(__nv_bfloat162*)(row + 256 + c0 + 2 * cp) = lp;
    }
}

// ---------------------------------------------------------------------------
// proj_mma: 2-stage cp.async double-buffered bf16 mma GEMM, 12 virtual
// K-chunks over [hi|lo] storage: (Whi,Xhi)x4, (Whi,Xlo)x4, (Wlo,Xhi)x4.
// ---------------------------------------------------------------------------
__constant__ int ACH[12] = {0, 1, 2, 3, 0, 1, 2, 3, 4, 5, 6, 7};
__constant__ int BCH[12] = {0, 1, 2, 3, 4, 5, 6, 7, 0, 1, 2, 3};

__global__ void __launch_bounds__(256) proj_mma_kernel(
    const float* __restrict__ bq, const float* __restrict__ bk,
    const float* __restrict__ bv)
{
    char* smem = smem_raw;
    const uint32_t smem_base = smem_u32(smem);
    const int tid = threadIdx.x;
    const int wid = tid >> 5, lane = tid & 31;
    const int warp_m = wid & 1;
    const int warp_n = wid >> 1;
    const int pt = blockIdx.x, mt = blockIdx.y, b = blockIdx.z;

    const char* Abase = (const char*)(g_wsplit + (size_t)mt * 128 * KP);
    const char* Bbase = (const char*)(g_xt + ((size_t)b * HWS + pt * 128) * KP);

    float acc[4][4][4];
    #pragma unroll
    for (int i = 0; i < 4; i++)
        #pragma unroll
        for (int j = 0; j < 4; j++)
            #pragma unroll
            for (int k = 0; k < 4; k++) acc[i][j][k] = 0.0f;

    const int a_row_in = lane & 15;
    const int a_kseg   = (lane >> 4) << 4;
    const int b_row_in = (lane & 7) + ((lane >> 4) << 3);
    const int b_kseg   = ((lane >> 3) & 1) << 4;

    const int ld_row = tid >> 3, ld_seg = tid & 7;

    auto issue = [&](int ch, int st) {
        const size_t a0b = (size_t)ACH[ch] * 128;   // 64 bf16 = 128B per chunk
        const size_t b0b = (size_t)BCH[ch] * 128;
        const uint32_t sb = smem_base + st * 32768;
        #pragma unroll
        for (int r = 0; r < 4; r++) {
            int row = ld_row + r * 32;
            uint32_t so = sw128((uint32_t)(row * 128 + ld_seg * 16));
            CP_ASYNC16(sb + so,         Abase + (size_t)row * (KP * 2) + a0b + ld_seg * 16);
            CP_ASYNC16(sb + 16384 + so, Bbase + (size_t)row * (KP * 2) + b0b + ld_seg * 16);
        }
    };

    issue(0, 0);
    CP_COMMIT();

    for (int ch = 0; ch < 12; ch++) {
        const int st = ch & 1;
        if (ch + 1 < 12) issue(ch + 1, st ^ 1);
        CP_COMMIT();
        CP_WAIT1();
        __syncthreads();

        const uint32_t sA_u = smem_base + st * 32768;
        const uint32_t sB_u = sA_u + 16384;
        #pragma unroll
        for (int kk = 0; kk < 4; kk++) {
            uint32_t af[4][4];
            #pragma unroll
            for (int mi = 0; mi < 4; mi++) {
                int row = warp_m * 64 + mi * 16 + a_row_in;
                ldmatrix_x4(af[mi][0], af[mi][1], af[mi][2], af[mi][3],
                            sA_u + sw128((uint32_t)(row * 128 + kk * 32 + a_kseg)));
            }
            uint32_t bf[2][4];
            #pragma unroll
            for (int ni16 = 0; ni16 < 2; ni16++) {
                int row = warp_n * 32 + ni16 * 16 + b_row_in;
                ldmatrix_x4(bf[ni16][0], bf[ni16][1], bf[ni16][2], bf[ni16][3],
                            sB_u + sw128((uint32_t)(row * 128 + kk * 32 + b_kseg)));
            }
            #pragma unroll
            for (int mi = 0; mi < 4; mi++)
                #pragma unroll
                for (int ni = 0; ni < 4; ni++)
                    mma_bf16(acc[mi][ni][0], acc[mi][ni][1], acc[mi][ni][2], acc[mi][ni][3],
                             af[mi][0], af[mi][1], af[mi][2], af[mi][3],
                             bf[ni >> 1][(ni & 1) * 2 + 0], bf[ni >> 1][(ni & 1) * 2 + 1]);
        }
        __syncthreads();
    }

    const int p0 = pt * 128 + warp_n * 32 + 2 * (lane & 3);
    #pragma unroll
    for (int mi = 0; mi < 4; mi++) {
        #pragma unroll
        for (int half = 0; half < 2; half++) {
            int m = mt * 128 + warp_m * 64 + mi * 16 + (lane >> 2) + half * 8;
            float bias;
            float* dst;
            if (m < 256)      { bias = bv[m];       dst = &g_v[((size_t)b * 256 + m) * HWS]; }
            else if (m < 288) { bias = bq[m - 256]; dst = &g_q[((size_t)b * 32 + (m - 256)) * HWS]; }
            else if (m < 320) { bias = bk[m - 288]; dst = &g_k[((size_t)b * 32 + (m - 288)) * HWS]; }
            else continue;
            #pragma unroll
            for (int ni = 0; ni < 4; ni++) {
                float2 v = make_float2(acc[mi][ni][half * 2 + 0] + bias,
                                       acc[mi][ni][half * 2 + 1] + bias);
                *(float2*)&dst[p0 + ni * 8] = v;
            }
        }
    }
}

// ---------------------------------------------------------------------------
// transpose (unchanged)
// ---------------------------------------------------------------------------
__global__ void transpose_kernel()
{
    __shared__ float sm[32][33];
    const int plane = blockIdx.z;
    const float* src;
    float* dst;
    if (plane < 128)      { src = g_q + (size_t)plane * HWS;        dst = g_qT + (size_t)plane * HWS; }
    else if (plane < 256) { src = g_k + (size_t)(plane - 128) * HWS; dst = g_kT + (size_t)(plane - 128) * HWS; }
    else                  { src = g_v + (size_t)(plane - 256) * HWS; dst = g_vT + (size_t)(plane - 256) * HWS; }
    const int ti = blockIdx.y * 32, tj = blockIdx.x * 32;
    const int t = threadIdx.x;
    const int cc = t & 31, r0 = t >> 5;
    #pragma unroll
    for (int p = 0; p < 4; p++) {
        int r = r0 + p * 8;
        sm[r][cc] = src[(size_t)(ti + r) * WW + tj + cc];
    }
    __syncthreads();
    #pragma unroll
    for (int p = 0; p < 4; p++) {
        int r = r0 + p * 8;
        dst[(size_t)(tj + r) * HH + ti + cc] = sm[cc][r];
    }
}

// ---------------------------------------------------------------------------
// Tensor-core criss-cross attention, register softmax, single-fp16 V.
// smem: [0,32K)   P fp16 [g][j], 256B rows, sw256
//       [32K,48K) Vhi fp16 [c][g] 256B rows sw256
//       [48K,64K) A op (K') bf16 [g][24+pad] 128B rows sw128
//       [64K,80K) B op (Q')
//       [80K,81K) ssum[2][128] fp32
// ---------------------------------------------------------------------------
#define AT_P    0
#define AT_VHI  32768
#define AT_A    49152
#define AT_B    65536
#define AT_SSUM 81920
#define AT_SMEM (81920 + 1024)

__global__ void __launch_bounds__(256, 2) attn_kernel(
    const float* __restrict__ x, const float* __restrict__ gamma,
    float* __restrict__ out)
{
    char* smem = smem_raw;
    float* ssum = (float*)(smem + AT_SSUM);   // ssum[em*128 + j]

    const int i  = blockIdx.x;
    const int bh = blockIdx.y;
    const int b = bh >> 2, h = bh & 3;
    const int tid = threadIdx.x;
    const int wid = tid >> 5, lane = tid & 31;

    const int a_row_in = lane & 15;
    const int a_kseg   = (lane >> 4) << 4;
    const int b_row_in = (lane & 7) + ((lane >> 4) << 3);
    const int b_kseg   = ((lane >> 3) & 1) << 4;

    const int em = wid & 1, en = wid >> 1;

    const size_t qk_base = ((size_t)b * 32 + h * 8) * HWS;
    const size_t v_base  = ((size_t)b * 256 + h * 64) * HWS;

    float acc[8][4];
    #pragma unroll
    for (int ni = 0; ni < 8; ni++)
        #pragma unroll
        for (int k = 0; k < 4; k++) acc[ni][k] = 0.0f;

    for (int phase = 0; phase < 2; phase++) {
        const float* Qp = phase ? g_qT : g_q;
        const float* Kp = phase ? g_kT : g_k;
        const float* Vp = phase ? g_vT : g_v;

        // ---- build energy operands A=K', B=Q' (bf16 3-term split) ----
        {
            const int g = tid & 127, hf = tid >> 7;
            #pragma unroll
            for (int cc = 0; cc < 4; cc++) {
                int c = hf * 4 + cc;
                size_t off = qk_base + (size_t)c * HWS + (size_t)i * WW + g;
                float kv = Kp[off], qv = Qp[off];
                __nv_bfloat16 khi = __float2bfloat16(kv);
                __nv_bfloat16 klo = __float2bfloat16(kv - __bfloat162float(khi));
                __nv_bfloat16 qhi = __float2bfloat16(qv);
                __nv_bfloat16 qlo = __float2bfloat16(qv - __bfloat162float(qhi));
                *(__nv_bfloat16*)(smem + AT_A + sw128((uint32_t)(g * 128 + c * 2)))        = khi;
                *(__nv_bfloat16*)(smem + AT_A + sw128((uint32_t)(g * 128 + (c + 8) * 2)))  = khi;
                *(__nv_bfloat16*)(smem + AT_A + sw128((uint32_t)(g * 128 + (c + 16) * 2))) = klo;
                *(__nv_bfloat16*)(smem + AT_B + sw128((uint32_t)(g * 128 + c * 2)))        = qhi;
                *(__nv_bfloat16*)(smem + AT_B + sw128((uint32_t)(g * 128 + (c + 8) * 2)))  = qlo;
                *(__nv_bfloat16*)(smem + AT_B + sw128((uint32_t)(g * 128 + (c + 16) * 2))) = qhi;
            }
            uint32_t pad = sw128((uint32_t)(g * 128 + 48));
            if (hf == 0) *(uint4*)(smem + AT_A + pad) = make_uint4(0, 0, 0, 0);
            else         *(uint4*)(smem + AT_B + pad) = make_uint4(0, 0, 0, 0);
        }
        // ---- build V fp16 [c][g] ----
        for (int idx = tid; idx < 2048; idx += 256) {
            int c = idx >> 5, g4 = (idx & 31) * 4;
            float4 v = *(const float4*)&Vp[v_base + (size_t)c * HWS + (size_t)i * WW + g4];
            __half2 hp0 = __floats2half2_rn(v.x, v.y);
            __half2 hp1 = __floats2half2_rn(v.z, v.w);
            uint32_t base = (uint32_t)(c * 256 + g4 * 2);
            *(uint32_t*)(smem + AT_VHI + sw256(base))     = *(uint32_t*)&hp0;
            *(uint32_t*)(smem + AT_VHI + sw256(base + 4)) = *(uint32_t*)&hp1;
        }
        __syncthreads();

        // ---- energy mma ----
        float ef[4][4][4];
        #pragma unroll
        for (int mi = 0; mi < 4; mi++)
            #pragma unroll
            for (int ni = 0; ni < 4; ni++)
                #pragma unroll
                for (int k = 0; k < 4; k++) ef[mi][ni][k] = 0.0f;
        {
            const uint32_t sA_u = smem_u32(smem + AT_A);
            const uint32_t sB_u = smem_u32(smem + AT_B);
            #pragma unroll
            for (int ks = 0; ks < 2; ks++) {
                uint32_t af[4][4];
                #pragma unroll
                for (int mi = 0; mi < 4; mi++) {
                    int row = em * 64 + mi * 16 + a_row_in;
                    ldmatrix_x4(af[mi][0], af[mi][1], af[mi][2], af[mi][3],
                                sA_u + sw128((uint32_t)(row * 128 + ks * 32 + a_kseg)));
                }
                uint32_t bfr[2][4];
                #pragma unroll
                for (int n16 = 0; n16 < 2; n16++) {
                    int row = en * 32 + n16 * 16 + b_row_in;
                    ldmatrix_x4(bfr[n16][0], bfr[n16][1], bfr[n16][2], bfr[n16][3],
                                sB_u + sw128((uint32_t)(row * 128 + ks * 32 + b_kseg)));
                }
                #pragma unroll
                for (int mi = 0; mi < 4; mi++)
                    #pragma unroll
                    for (int ni = 0; ni < 4; ni++)
                        mma_bf16(ef[mi][ni][0], ef[mi][ni][1], ef[mi][ni][2], ef[mi][ni][3],
                                 af[mi][0], af[mi][1], af[mi][2], af[mi][3],
                                 bfr[ni >> 1][(ni & 1) * 2 + 0], bfr[ni >> 1][(ni & 1) * 2 + 1]);
            }
        }

        // ---- exp in registers + per-j column sums ----
        float psum[4][2];
        #pragma unroll
        for (int ni = 0; ni < 4; ni++) { psum[ni][0] = 0.0f; psum[ni][1] = 0.0f; }
        #pragma unroll
        for (int mi = 0; mi < 4; mi++)
            #pragma unroll
            for (int ni = 0; ni < 4; ni++) {
                ef[mi][ni][0] = __expf(ef[mi][ni][0]);
                ef[mi][ni][1] = __expf(ef[mi][ni][1]);
                ef[mi][ni][2] = __expf(ef[mi][ni][2]);
                ef[mi][ni][3] = __expf(ef[mi][ni][3]);
                psum[ni][0] += ef[mi][ni][0] + ef[mi][ni][2];
                psum[ni][1] += ef[mi][ni][1] + ef[mi][ni][3];
            }
        #pragma unroll
        for (int ni = 0; ni < 4; ni++) {
            #pragma unroll
            for (int d = 4; d <= 16; d <<= 1) {
                psum[ni][0] += __shfl_xor_sync(0xffffffffu, psum[ni][0], d);
                psum[ni][1] += __shfl_xor_sync(0xffffffffu, psum[ni][1], d);
            }
        }
        if ((lane >> 2) == 0) {
            #pragma unroll
            for (int ni = 0; ni < 4; ni++) {
                int j0 = en * 32 + ni * 8 + (lane & 3) * 2;
                *(float2*)&ssum[em * 128 + j0] = make_float2(psum[ni][0], psum[ni][1]);
            }
        }
        __syncthreads();

        // ---- normalize + store P fp16 [g][j] ----
        #pragma unroll
        for (int ni = 0; ni < 4; ni++) {
            int j0 = en * 32 + ni * 8 + (lane & 3) * 2;
            float2 sa = *(float2*)&ssum[j0];
            float2 sb = *(float2*)&ssum[128 + j0];
            float is0 = 1.0f / (sa.x + sb.x);
            float is1 = 1.0f / (sa.y + sb.y);
            #pragma unroll
            for (int mi = 0; mi < 4; mi++) {
                int g0 = em * 64 + mi * 16 + (lane >> 2);
                __half2 p0 = __floats2half2_rn(ef[mi][ni][0] * is0, ef[mi][ni][1] * is1);
                __half2 p1 = __floats2half2_rn(ef[mi][ni][2] * is0, ef[mi][ni][3] * is1);
                *(uint32_t*)(smem + AT_P + sw256((uint32_t)(g0 * 256 + j0 * 2)))       = *(uint32_t*)&p0;
                *(uint32_t*)(smem + AT_P + sw256((uint32_t)((g0 + 8) * 256 + j0 * 2))) = *(uint32_t*)&p1;
            }
        }
        __syncthreads();

        // ---- O mma: A = P (m=j, k=g, trans-load), B = V (n=c, k=g) ----
        {
            const uint32_t sP_u = smem_u32(smem + AT_P);
            const uint32_t sV_u = smem_u32(smem + AT_VHI);
            const int p_row_in = (lane & 7) + (((lane >> 4) & 1) << 3);
            const int p_col    = (wid << 4) + (((lane >> 3) & 1) << 3);
            #pragma unroll
            for (int ks = 0; ks < 8; ks++) {
                uint32_t af[4];
                {
                    int row = ks * 16 + p_row_in;
                    ldmatrix_x4_trans(af[0], af[1], af[2], af[3],
                                      sP_u + sw256((uint32_t)(row * 256 + p_col * 2)));
                }
                uint32_t bfr[4][4];
                #pragma unroll
                for (int n16 = 0; n16 < 4; n16++) {
                    int row = n16 * 16 + b_row_in;
                    ldmatrix_x4(bfr[n16][0], bfr[n16][1], bfr[n16][2], bfr[n16][3],
                                sV_u + sw256((uint32_t)(row * 256 + ks * 32) + (uint32_t)b_kseg));
                }
                #pragma unroll
                for (int n16 = 0; n16 < 4; n16++)
                    #pragma unroll
                    for (int sub = 0; sub < 2; sub++)
                        mma_f16(acc[n16 * 2 + sub][0], acc[n16 * 2 + sub][1],
                                acc[n16 * 2 + sub][2], acc[n16 * 2 + sub][3],
                                af[0], af[1], af[2], af[3],
                                bfr[n16][sub * 2 + 0], bfr[n16][sub * 2 + 1]);
            }
        }
        __syncthreads();
    }

    // ---- epilogue ----
    const float gm = gamma[0];
    const size_t bch = (size_t)b * 256 + h * 64;
    const int jb = wid * 16 + (lane >> 2);
    #pragma unroll
    for (int ni = 0; ni < 8; ni++) {
        int c0 = ni * 8 + (lane & 3) * 2;
        #pragma unroll
        for (int hf = 0; hf < 2; hf++) {
            int j = jb + hf * 8;
            size_t off0 = ((bch + c0) * HH + i) * WW + j;
            size_t off1 = off0 + HWS;
            out[off0] = gm * acc[ni][hf * 2 + 0] + x[off0];
            out[off1] = gm * acc[ni][hf * 2 + 1] + x[off1];
        }
    }
}

// ---------------------------------------------------------------------------
extern "C" void kernel_launch(void* const* d_in, const int* in_sizes, int n_in,
                              void* d_out, int out_size)
{
    const float* x     = (const float*)d_in[0];
    const float* Wq    = (const float*)d_in[1];
    const float* bq    = (const float*)d_in[2];
    const float* Wk    = (const float*)d_in[3];
    const float* bk    = (const float*)d_in[4];
    const float* Wv    = (const float*)d_in[5];
    const float* bv    = (const float*)d_in[6];
    const float* gamma = (const float*)d_in[7];
    float* out = (float*)d_out;

    cudaFuncSetAttribute(attn_kernel, cudaFuncAttributeMaxDynamicSharedMemorySize,
                         AT_SMEM);
    cudaFuncSetAttribute(proj_mma_kernel, cudaFuncAttributeMaxDynamicSharedMemorySize,
                         65536);

    prep_w_kernel<<<384, 256>>>(Wq, Wk, Wv);
    prep_x_kernel<<<dim3(256, 4, NB), 256>>>(x);
    proj_mma_kernel<<<dim3(128, 3, NB), 256, 65536>>>(bq, bk, bv);
    transpose_kernel<<<dim3(4, 4, NB * 320), 256>>>();
    attn_kernel<<<dim3(HH, NB * 4), 256, AT_SMEM>>>(x, gamma, out);
}

// round 9
// speedup vs baseline: 3.3755x; 1.0399x over previous
#include <cuda_runtime.h>
#include <cuda_bf16.h>
#include <cuda_fp16.h>
#include <cstdint>

#define HH 128
#define WW 128
#define HWS 16384
#define NB 4
#define KP 512   // split-K storage: [hi(256) | lo(256)]; 12 virtual chunks at GEMM

// ---------------- scratch (device globals; allocation-free rule) ------------
__device__ __align__(16) __nv_bfloat16 g_qhi[(size_t)NB * 32 * HWS];
__device__ __align__(16) __nv_bfloat16 g_qlo[(size_t)NB * 32 * HWS];
__device__ __align__(16) __nv_bfloat16 g_khi[(size_t)NB * 32 * HWS];
__device__ __align__(16) __nv_bfloat16 g_klo[(size_t)NB * 32 * HWS];
__device__ __align__(16) __nv_bfloat16 g_qhiT[(size_t)NB * 32 * HWS];
__device__ __align__(16) __nv_bfloat16 g_qloT[(size_t)NB * 32 * HWS];
__device__ __align__(16) __nv_bfloat16 g_khiT[(size_t)NB * 32 * HWS];
__device__ __align__(16) __nv_bfloat16 g_kloT[(size_t)NB * 32 * HWS];
__device__ __align__(16) __half g_v [(size_t)NB * 256 * HWS];
__device__ __align__(16) __half g_vT[(size_t)NB * 256 * HWS];
__device__ __align__(16) __nv_bfloat16 g_wsplit[(size_t)384 * KP];       // [m][hi|lo]
__device__ __align__(16) __nv_bfloat16 g_xt[(size_t)NB * HWS * KP];      // [b][p][hi|lo]

// single TU-wide dynamic smem symbol (char; cast per-kernel)
extern __shared__ __align__(1024) char smem_raw[];

static __device__ __forceinline__ uint32_t sw128(uint32_t off) {
    return off ^ ((off >> 3) & 0x70);
}
static __device__ __forceinline__ uint32_t sw256(uint32_t off) {
    return off ^ (((off >> 8) & 7) << 4);
}
__device__ __forceinline__ uint32_t smem_u32(const void* p) {
    uint32_t a;
    asm("{ .reg .u64 t; cvta.to.shared.u64 t, %1; cvt.u32.u64 %0, t; }"
        : "=r"(a) : "l"(p));
    return a;
}
__device__ __forceinline__ void ldmatrix_x4(uint32_t& r0, uint32_t& r1,
                                            uint32_t& r2, uint32_t& r3, uint32_t addr) {
    asm volatile("ldmatrix.sync.aligned.m8n8.x4.shared.b16 {%0,%1,%2,%3}, [%4];"
                 : "=r"(r0), "=r"(r1), "=r"(r2), "=r"(r3) : "r"(addr));
}
__device__ __forceinline__ void ldmatrix_x4_trans(uint32_t& r0, uint32_t& r1,
                                                  uint32_t& r2, uint32_t& r3, uint32_t addr) {
    asm volatile("ldmatrix.sync.aligned.m8n8.x4.trans.shared.b16 {%0,%1,%2,%3}, [%4];"
                 : "=r"(r0), "=r"(r1), "=r"(r2), "=r"(r3) : "r"(addr));
}
__device__ __forceinline__ void mma_bf16(float& d0, float& d1, float& d2, float& d3,
                                         uint32_t a0, uint32_t a1, uint32_t a2, uint32_t a3,
                                         uint32_t b0, uint32_t b1) {
    asm volatile("mma.sync.aligned.m16n8k16.row.col.f32.bf16.bf16.f32 "
                 "{%0,%1,%2,%3}, {%4,%5,%6,%7}, {%8,%9}, {%0,%1,%2,%3};"
                 : "+f"(d0), "+f"(d1), "+f"(d2), "+f"(d3)
                 : "r"(a0), "r"(a1), "r"(a2), "r"(a3), "r"(b0), "r"(b1));
}
__device__ __forceinline__ void mma_f16(float& d0, float& d1, float& d2, float& d3,
                                        uint32_t a0, uint32_t a1, uint32_t a2, uint32_t a3,
                                        uint32_t b0, uint32_t b1) {
    asm volatile("mma.sync.aligned.m16n8k16.row.col.f32.f16.f16.f32 "
                 "{%0,%1,%2,%3}, {%4,%5,%6,%7}, {%8,%9}, {%0,%1,%2,%3};"
                 : "+f"(d0), "+f"(d1), "+f"(d2), "+f"(d3)
                 : "r"(a0), "r"(a1), "r"(a2), "r"(a3), "r"(b0), "r"(b1));
}
#define CP_ASYNC16(dst, src) \
    asm volatile("cp.async.cg.shared.global [%0], [%1], 16;" :: "r"(dst), "l"(src))
#define CP_COMMIT() asm volatile("cp.async.commit_group;" ::: "memory")
#define CP_WAIT1()  asm volatile("cp.async.wait_group 1;" ::: "memory")
#define CP_WAIT0()  asm volatile("cp.async.wait_group 0;" ::: "memory")

// ---------------------------------------------------------------------------
// prep_w: W' bf16 [384][512]; rows 0-255 Wv, 256-287 Wq, 288-319 Wk, 320-383 0
// ---------------------------------------------------------------------------
__global__ void prep_w_kernel(const float* __restrict__ Wq, const float* __restrict__ Wk,
                              const float* __restrict__ Wv)
{
    const int m = blockIdx.x;
    const int c = threadIdx.x;
    float w = 0.0f;
    if (m < 256)      w = Wv[m * 256 + c];
    else if (m < 288) w = Wq[(m - 256) * 256 + c];
    else if (m < 320) w = Wk[(m - 288) * 256 + c];
    __nv_bfloat16 hi = __float2bfloat16(w);
    __nv_bfloat16 lo = __float2bfloat16(w - __bfloat162float(hi));
    g_wsplit[(size_t)m * KP + c]       = hi;
    g_wsplit[(size_t)m * KP + 256 + c] = lo;
}

// ---------------------------------------------------------------------------
// prep_x: XT' bf16 [b][p][512]: cols [0:256)=hi, [256:512)=lo
// ---------------------------------------------------------------------------
__global__ void prep_x_kernel(const float* __restrict__ x)
{
    __shared__ float sm[64][65];
    const int b = blockIdx.z, ct = blockIdx.y, pt = blockIdx.x;
    const int c0 = ct * 64, p0 = pt * 64;
    const int t = threadIdx.x;
    const int pj = t & 63, ci0 = t >> 6;
    const float* xb = x + ((size_t)b * 256 + c0) * HWS + p0;
    #pragma unroll
    for (int i = 0; i < 16; i++) {
        int ci = ci0 + i * 4;
        sm[ci][pj] = xb[(size_t)ci * HWS + pj];
    }
    __syncthreads();
    const int cp = t & 31, pl = t >> 5;
    #pragma unroll
    for (int i = 0; i < 8; i++) {
        int p = pl + i * 8;
        float f0 = sm[2 * cp][p], f1 = sm[2 * cp + 1][p];
        __nv_bfloat16 h0 = __float2bfloat16(f0), h1 = __float2bfloat16(f1);
        __nv_bfloat16 l0 = __float2bfloat16(f0 - __bfloat162float(h0));
        __nv_bfloat16 l1 = __float2bfloat16(f1 - __bfloat162float(h1));
        __nv_bfloat162 hp; hp.x = h0; hp.y = h1;
        __nv_bfloat162 lp; lp.x = l0; lp.y = l1;
        __nv_bfloat16* row = g_xt + ((size_t)b * HWS + p0 + p) * KP;
        *(__nv_bfloat162*)(row + c0 + 2 * cp)       = hp;
        *(__nv_bfloat162*)(row + 256 + c0 + 2 * cp) = lp;
    }
}

// ---------------------------------------------------------------------------
// proj_mma: 2-stage cp.async double-buffered bf16 mma GEMM; epilogue writes
// pre-split operand planes (q/k bf16 hi+lo, v fp16).
// ---------------------------------------------------------------------------
__constant__ int ACH[12] = {0, 1, 2, 3, 0, 1, 2, 3, 4, 5, 6, 7};
__constant__ int BCH[12] = {0, 1, 2, 3, 4, 5, 6, 7, 0, 1, 2, 3};

__global__ void __launch_bounds__(256) proj_mma_kernel(
    const float* __restrict__ bq, const float* __restrict__ bk,
    const float* __restrict__ bv)
{
    char* smem = smem_raw;
    const uint32_t smem_base = smem_u32(smem);
    const int tid = threadIdx.x;
    const int wid = tid >> 5, lane = tid & 31;
    const int warp_m = wid & 1;
    const int warp_n = wid >> 1;
    const int pt = blockIdx.x, mt = blockIdx.y, b = blockIdx.z;

    const char* Abase = (const char*)(g_wsplit + (size_t)mt * 128 * KP);
    const char* Bbase = (const char*)(g_xt + ((size_t)b * HWS + pt * 128) * KP);

    float acc[4][4][4];
    #pragma unroll
    for (int i = 0; i < 4; i++)
        #pragma unroll
        for (int j = 0; j < 4; j++)
            #pragma unroll
            for (int k = 0; k < 4; k++) acc[i][j][k] = 0.0f;

    const int a_row_in = lane & 15;
    const int a_kseg   = (lane >> 4) << 4;
    const int b_row_in = (lane & 7) + ((lane >> 4) << 3);
    const int b_kseg   = ((lane >> 3) & 1) << 4;

    const int ld_row = tid >> 3, ld_seg = tid & 7;

    auto issue = [&](int ch, int st) {
        const size_t a0b = (size_t)ACH[ch] * 128;
        const size_t b0b = (size_t)BCH[ch] * 128;
        const uint32_t sb = smem_base + st * 32768;
        #pragma unroll
        for (int r = 0; r < 4; r++) {
            int row = ld_row + r * 32;
            uint32_t so = sw128((uint32_t)(row * 128 + ld_seg * 16));
            CP_ASYNC16(sb + so,         Abase + (size_t)row * (KP * 2) + a0b + ld_seg * 16);
            CP_ASYNC16(sb + 16384 + so, Bbase + (size_t)row * (KP * 2) + b0b + ld_seg * 16);
        }
    };

    issue(0, 0);
    CP_COMMIT();

    for (int ch = 0; ch < 12; ch++) {
        const int st = ch & 1;
        if (ch + 1 < 12) issue(ch + 1, st ^ 1);
        CP_COMMIT();
        CP_WAIT1();
        __syncthreads();

        const uint32_t sA_u = smem_base + st * 32768;
        const uint32_t sB_u = sA_u + 16384;
        #pragma unroll
        for (int kk = 0; kk < 4; kk++) {
            uint32_t af[4][4];
            #pragma unroll
            for (int mi = 0; mi < 4; mi++) {
                int row = warp_m * 64 + mi * 16 + a_row_in;
                ldmatrix_x4(af[mi][0], af[mi][1], af[mi][2], af[mi][3],
                            sA_u + sw128((uint32_t)(row * 128 + kk * 32 + a_kseg)));
            }
            uint32_t bf[2][4];
            #pragma unroll
            for (int ni16 = 0; ni16 < 2; ni16++) {
                int row = warp_n * 32 + ni16 * 16 + b_row_in;
                ldmatrix_x4(bf[ni16][0], bf[ni16][1], bf[ni16][2], bf[ni16][3],
                            sB_u + sw128((uint32_t)(row * 128 + kk * 32 + b_kseg)));
            }
            #pragma unroll
            for (int mi = 0; mi < 4; mi++)
                #pragma unroll
                for (int ni = 0; ni < 4; ni++)
                    mma_bf16(acc[mi][ni][0], acc[mi][ni][1], acc[mi][ni][2], acc[mi][ni][3],
                             af[mi][0], af[mi][1], af[mi][2], af[mi][3],
                             bf[ni >> 1][(ni & 1) * 2 + 0], bf[ni >> 1][(ni & 1) * 2 + 1]);
        }
        __syncthreads();
    }

    const int p0 = pt * 128 + warp_n * 32 + 2 * (lane & 3);
    #pragma unroll
    for (int mi = 0; mi < 4; mi++) {
        #pragma unroll
        for (int half = 0; half < 2; half++) {
            int m = mt * 128 + warp_m * 64 + mi * 16 + (lane >> 2) + half * 8;
            #pragma unroll
            for (int ni = 0; ni < 4; ni++) {
                float v0 = acc[mi][ni][half * 2 + 0];
                float v1 = acc[mi][ni][half * 2 + 1];
                int p = p0 + ni * 8;
                if (m < 256) {
                    float bias = bv[m];
                    __half2 hv = __floats2half2_rn(v0 + bias, v1 + bias);
                    *(__half2*)&g_v[((size_t)b * 256 + m) * HWS + p] = hv;
                } else if (m < 320) {
                    const bool isq = (m < 288);
                    int c = isq ? (m - 256) : (m - 288);
                    float bias = isq ? bq[c] : bk[c];
                    float f0 = v0 + bias, f1 = v1 + bias;
                    __nv_bfloat16 h0 = __float2bfloat16(f0), h1 = __float2bfloat16(f1);
                    __nv_bfloat16 l0 = __float2bfloat16(f0 - __bfloat162float(h0));
                    __nv_bfloat16 l1 = __float2bfloat16(f1 - __bfloat162float(h1));
                    __nv_bfloat162 hp; hp.x = h0; hp.y = h1;
                    __nv_bfloat162 lp; lp.x = l0; lp.y = l1;
                    size_t off = ((size_t)b * 32 + c) * HWS + p;
                    if (isq) {
                        *(__nv_bfloat162*)&g_qhi[off] = hp;
                        *(__nv_bfloat162*)&g_qlo[off] = lp;
                    } else {
                        *(__nv_bfloat162*)&g_khi[off] = hp;
                        *(__nv_bfloat162*)&g_klo[off] = lp;
                    }
                }
            }
        }
    }
}

// ---------------------------------------------------------------------------
// transpose: 16-bit planes [H][W] -> [W][H].
// plane: 0-127 qhi, 128-255 qlo, 256-383 khi, 384-511 klo, 512-1535 v (fp16)
// ---------------------------------------------------------------------------
__global__ void transpose_kernel()
{
    __shared__ uint16_t sm[32][33];
    const int plane = blockIdx.z;
    const uint16_t* src;
    uint16_t* dst;
    if (plane < 512) {
        int t = plane >> 7, ch = plane & 127;
        const __nv_bfloat16* s;
        __nv_bfloat16* d;
        switch (t) {
            case 0:  s = g_qhi; d = g_qhiT; break;
            case 1:  s = g_qlo; d = g_qloT; break;
            case 2:  s = g_khi; d = g_khiT; break;
            default: s = g_klo; d = g_kloT; break;
        }
        src = (const uint16_t*)(s + (size_t)ch * HWS);
        dst = (uint16_t*)(d + (size_t)ch * HWS);
    } else {
        int ch = plane - 512;
        src = (const uint16_t*)(g_v + (size_t)ch * HWS);
        dst = (uint16_t*)(g_vT + (size_t)ch * HWS);
    }
    const int ti = blockIdx.y * 32, tj = blockIdx.x * 32;
    const int t = threadIdx.x;
    const int cc = t & 31, r0 = t >> 5;
    #pragma unroll
    for (int p = 0; p < 4; p++) {
        int r = r0 + p * 8;
        sm[r][cc] = src[(size_t)(ti + r) * WW + tj + cc];
    }
    __syncthreads();
    #pragma unroll
    for (int p = 0; p < 4; p++) {
        int r = r0 + p * 8;
        dst[(size_t)(tj + r) * HH + ti + cc] = sm[cc][r];
    }
}

// ---------------------------------------------------------------------------
// Tensor-core criss-cross attention; operands pre-split, loads = cp.async.
// smem: [0,32K)   P fp16 [g][j], 256B rows, sw256
//       [32K,48K) V fp16 [c][g], 256B rows, sw256
//       [48K,56K) A-energy bf16 [c'][g] 32 rows x 256B sw256
//                 rows 0-7 khi, 8-15 khi, 16-23 klo, 24-31 zero
//       [56K,64K) B-energy: 0-7 qhi, 8-15 qlo, 16-23 qhi, 24-31 zero
//       [64K,65K) ssum[2][128] fp32
// ---------------------------------------------------------------------------
#define AT_P    0
#define AT_V    32768
#define AT_A    49152
#define AT_B    57344
#define AT_SSUM 65536
#define AT_SMEM (65536 + 1024)

__global__ void __launch_bounds__(256, 2) attn_kernel(
    const float* __restrict__ x, const float* __restrict__ gamma,
    float* __restrict__ out)
{
    char* smem = smem_raw;
    float* ssum = (float*)(smem + AT_SSUM);

    const int i  = blockIdx.x;
    const int bh = blockIdx.y;
    const int b = bh >> 2, h = bh & 3;
    const int tid = threadIdx.x;
    const int wid = tid >> 5, lane = tid & 31;

    const uint32_t sP_u = smem_u32(smem + AT_P);
    const uint32_t sV_u = smem_u32(smem + AT_V);
    const uint32_t sA_u = smem_u32(smem + AT_A);
    const uint32_t sB_u = smem_u32(smem + AT_B);

    // V (B-operand, non-trans) lane addressing
    const int b_row_in = (lane & 7) + ((lane >> 4) << 3);
    const int b_kseg   = ((lane >> 3) & 1) << 4;
    // trans-ldmatrix lane addressing (A-style: quads m-lo/m-hi x k-lo/k-hi)
    const int tr_row_a = (lane & 7) + (((lane >> 4) & 1) << 3);
    const int tr_col_a = ((lane >> 3) & 1) << 3;
    // trans-ldmatrix lane addressing (B-style: quads k-lo/k-hi x n-lo/n-hi)
    const int tr_row_b = (lane & 7) + (((lane >> 3) & 1) << 3);
    const int tr_col_b = ((lane >> 4) & 1) << 3;

    const int em = wid & 1, en = wid >> 1;

    const int qkc0 = (b * 32 + h * 8);       // first of 8 qk channels
    const int vc0  = (b * 256 + h * 64);     // first of 64 v channels
    const int loff = i * 128;                // line offset (elements)

    // zero pad rows 24-31 of A and B (256 chunks of 16B; persists both phases)
    {
        int tile = tid >> 7, r = 24 + ((tid >> 4) & 7), chunk = tid & 15;
        uint32_t dst = (tile ? sB_u : sA_u) + sw256((uint32_t)(r * 256 + chunk * 16));
        *(uint4*)(smem + (dst - smem_u32(smem))) = make_uint4(0, 0, 0, 0);
    }

    float acc[8][4];
    #pragma unroll
    for (int ni = 0; ni < 8; ni++)
        #pragma unroll
        for (int k = 0; k < 4; k++) acc[ni][k] = 0.0f;

    for (int phase = 0; phase < 2; phase++) {
        const __nv_bfloat16* Khi = phase ? g_khiT : g_khi;
        const __nv_bfloat16* Klo = phase ? g_kloT : g_klo;
        const __nv_bfloat16* Qhi = phase ? g_qhiT : g_qhi;
        const __nv_bfloat16* Qlo = phase ? g_qloT : g_qlo;
        const __half*        Vp  = phase ? g_vT   : g_v;

        // ---- cp.async all operands ----
        #pragma unroll
        for (int it = 0; it < 3; it++) {          // A+B: 48 rows x 16 chunks
            int idx = tid + it * 256;
            int rr2 = idx >> 4, chunk = idx & 15;
            int tile = rr2 >= 24;
            int r = tile ? (rr2 - 24) : rr2;      // 0..23
            int c = r & 7;
            const __nv_bfloat16* src;
            if (!tile) src = (r < 16) ? Khi : Klo;
            else       src = (r >= 8 && r < 16) ? Qlo : Qhi;
            const char* gsrc = (const char*)(src + (size_t)(qkc0 + c) * HWS + loff) + chunk * 16;
            uint32_t dst = (tile ? sB_u : sA_u) + sw256((uint32_t)(r * 256 + chunk * 16));
            CP_ASYNC16(dst, gsrc);
        }
        #pragma unroll
        for (int it = 0; it < 4; it++) {          // V: 64 rows x 16 chunks
            int idx = tid + it * 256;
            int c = idx >> 4, chunk = idx & 15;
            const char* gsrc = (const char*)(Vp + (size_t)(vc0 + c) * HWS + loff) + chunk * 16;
            CP_ASYNC16(sV_u + sw256((uint32_t)(c * 256 + chunk * 16)), gsrc);
        }
        CP_COMMIT();
        CP_WAIT0();
        __syncthreads();

        // ---- energy mma: A,B via trans-ldmatrix from [c'][g] tiles ----
        float ef[4][4][4];
        #pragma unroll
        for (int mi = 0; mi < 4; mi++)
            #pragma unroll
            for (int ni = 0; ni < 4; ni++)
                #pragma unroll
                for (int k = 0; k < 4; k++) ef[mi][ni][k] = 0.0f;
        #pragma unroll
        for (int ks = 0; ks < 2; ks++) {
            uint32_t af[4][4];
            #pragma unroll
            for (int mi = 0; mi < 4; mi++) {
                int row = ks * 16 + tr_row_a;
                int col = em * 64 + mi * 16 + tr_col_a;
                ldmatrix_x4_trans(af[mi][0], af[mi][1], af[mi][2], af[mi][3],
                                  sA_u + sw256((uint32_t)(row * 256 + col * 2)));
            }
            uint32_t bfr[2][4];
            #pragma unroll
            for (int n16 = 0; n16 < 2; n16++) {
                int row = ks * 16 + tr_row_b;
                int col = en * 32 + n16 * 16 + tr_col_b;
                ldmatrix_x4_trans(bfr[n16][0], bfr[n16][1], bfr[n16][2], bfr[n16][3],
                                  sB_u + sw256((uint32_t)(row * 256 + col * 2)));
            }
            #pragma unroll
            for (int mi = 0; mi < 4; mi++)
                #pragma unroll
                for (int ni = 0; ni < 4; ni++)
                    mma_bf16(ef[mi][ni][0], ef[mi][ni][1], ef[mi][ni][2], ef[mi][ni][3],
                             af[mi][0], af[mi][1], af[mi][2], af[mi][3],
                             bfr[ni >> 1][(ni & 1) * 2 + 0], bfr[ni >> 1][(ni & 1) * 2 + 1]);
        }

        // ---- exp in registers + per-j column sums ----
        float psum[4][2];
        #pragma unroll
        for (int ni = 0; ni < 4; ni++) { psum[ni][0] = 0.0f; psum[ni][1] = 0.0f; }
        #pragma unroll
        for (int mi = 0; mi < 4; mi++)
            #pragma unroll
            for (int ni = 0; ni < 4; ni++) {
                ef[mi][ni][0] = __expf(ef[mi][ni][0]);
                ef[mi][ni][1] = __expf(ef[mi][ni][1]);
                ef[mi][ni][2] = __expf(ef[mi][ni][2]);
                ef[mi][ni][3] = __expf(ef[mi][ni][3]);
                psum[ni][0] += ef[mi][ni][0] + ef[mi][ni][2];
                psum[ni][1] += ef[mi][ni][1] + ef[mi][ni][3];
            }
        #pragma unroll
        for (int ni = 0; ni < 4; ni++) {
            #pragma unroll
            for (int d = 4; d <= 16; d <<= 1) {
                psum[ni][0] += __shfl_xor_sync(0xffffffffu, psum[ni][0], d);
                psum[ni][1] += __shfl_xor_sync(0xffffffffu, psum[ni][1], d);
            }
        }
        if ((lane >> 2) == 0) {
            #pragma unroll
            for (int ni = 0; ni < 4; ni++) {
                int j0 = en * 32 + ni * 8 + (lane & 3) * 2;
                *(float2*)&ssum[em * 128 + j0] = make_float2(psum[ni][0], psum[ni][1]);
            }
        }
        __syncthreads();

        // ---- normalize + store P fp16 [g][j] ----
        #pragma unroll
        for (int ni = 0; ni < 4; ni++) {
            int j0 = en * 32 + ni * 8 + (lane & 3) * 2;
            float2 sa = *(float2*)&ssum[j0];
            float2 sb = *(float2*)&ssum[128 + j0];
            float is0 = 1.0f / (sa.x + sb.x);
            float is1 = 1.0f / (sa.y + sb.y);
            #pragma unroll
            for (int mi = 0; mi < 4; mi++) {
                int g0 = em * 64 + mi * 16 + (lane >> 2);
                __half2 p0 = __floats2half2_rn(ef[mi][ni][0] * is0, ef[mi][ni][1] * is1);
                __half2 p1 = __floats2half2_rn(ef[mi][ni][2] * is0, ef[mi][ni][3] * is1);
                *(uint32_t*)(smem + AT_P + sw256((uint32_t)(g0 * 256 + j0 * 2)))       = *(uint32_t*)&p0;
                *(uint32_t*)(smem + AT_P + sw256((uint32_t)((g0 + 8) * 256 + j0 * 2))) = *(uint32_t*)&p1;
            }
        }
        __syncthreads();

        // ---- O mma: A = P (m=j, k=g, trans), B = V (n=c, k=g) ----
        {
            #pragma unroll
            for (int ks = 0; ks < 8; ks++) {
                uint32_t af[4];
                {
                    int row = ks * 16 + tr_row_a;
                    int col = wid * 16 + tr_col_a;
                    ldmatrix_x4_trans(af[0], af[1], af[2], af[3],
                                      sP_u + sw256((uint32_t)(row * 256 + col * 2)));
                }
                uint32_t bfr[4][4];
                #pragma unroll
                for (int n16 = 0; n16 < 4; n16++) {
                    int row = n16 * 16 + b_row_in;
                    ldmatrix_x4(bfr[n16][0], bfr[n16][1], bfr[n16][2], bfr[n16][3],
                                sV_u + sw256((uint32_t)(row * 256 + ks * 32) + (uint32_t)b_kseg));
                }
                #pragma unroll
                for (int n16 = 0; n16 < 4; n16++)
                    #pragma unroll
                    for (int sub = 0; sub < 2; sub++)
                        mma_f16(acc[n16 * 2 + sub][0], acc[n16 * 2 + sub][1],
                                acc[n16 * 2 + sub][2], acc[n16 * 2 + sub][3],
                                af[0], af[1], af[2], af[3],
                                bfr[n16][sub * 2 + 0], bfr[n16][sub * 2 + 1]);
            }
        }
        __syncthreads();
    }

    // ---- epilogue ----
    const float gm = gamma[0];
    const size_t bch = (size_t)b * 256 + h * 64;
    const int jb = wid * 16 + (lane >> 2);
    #pragma unroll
    for (int ni = 0; ni < 8; ni++) {
        int c0 = ni * 8 + (lane & 3) * 2;
        #pragma unroll
        for (int hf = 0; hf < 2; hf++) {
            int j = jb + hf * 8;
            size_t off0 = ((bch + c0) * HH + i) * WW + j;
            size_t off1 = off0 + HWS;
            out[off0] = gm * acc[ni][hf * 2 + 0] + x[off0];
            out[off1] = gm * acc[ni][hf * 2 + 1] + x[off1];
        }
    }
}

// ---------------------------------------------------------------------------
extern "C" void kernel_launch(void* const* d_in, const int* in_sizes, int n_in,
                              void* d_out, int out_size)
{
    const float* x     = (const float*)d_in[0];
    const float* Wq    = (const float*)d_in[1];
    const float* bq    = (const float*)d_in[2];
    const float* Wk    = (const float*)d_in[3];
    const float* bk    = (const float*)d_in[4];
    const float* Wv    = (const float*)d_in[5];
    const float* bv    = (const float*)d_in[6];
    const float* gamma = (const float*)d_in[7];
    float* out = (float*)d_out;

    cudaFuncSetAttribute(attn_kernel, cudaFuncAttributeMaxDynamicSharedMemorySize,
                         AT_SMEM);
    cudaFuncSetAttribute(proj_mma_kernel, cudaFuncAttributeMaxDynamicSharedMemorySize,
                         65536);

    prep_w_kernel<<<384, 256>>>(Wq, Wk, Wv);
    prep_x_kernel<<<dim3(256, 4, NB), 256>>>(x);
    proj_mma_kernel<<<dim3(128, 3, NB), 256, 65536>>>(bq, bk, bv);
    transpose_kernel<<<dim3(4, 4, 1536), 256>>>();
    attn_kernel<<<dim3(HH, NB * 4), 256, AT_SMEM>>>(x, gamma, out);
}

// round 10
// speedup vs baseline: 3.7941x; 1.1240x over previous
#include <cuda_runtime.h>
#include <cuda_bf16.h>
#include <cuda_fp16.h>
#include <cstdint>

#define HH 128
#define WW 128
#define HWS 16384
#define NB 4
#define KP 512   // split-K storage: [hi(256) | lo(256)]; 12 virtual chunks at GEMM

// ---------------- scratch (device globals; allocation-free rule) ------------
__device__ __align__(16) __nv_bfloat16 g_qhi[(size_t)NB * 32 * HWS];
__device__ __align__(16) __nv_bfloat16 g_qlo[(size_t)NB * 32 * HWS];
__device__ __align__(16) __nv_bfloat16 g_khi[(size_t)NB * 32 * HWS];
__device__ __align__(16) __nv_bfloat16 g_klo[(size_t)NB * 32 * HWS];
__device__ __align__(16) __nv_bfloat16 g_qhiT[(size_t)NB * 32 * HWS];
__device__ __align__(16) __nv_bfloat16 g_qloT[(size_t)NB * 32 * HWS];
__device__ __align__(16) __nv_bfloat16 g_khiT[(size_t)NB * 32 * HWS];
__device__ __align__(16) __nv_bfloat16 g_kloT[(size_t)NB * 32 * HWS];
__device__ __align__(16) __half g_v [(size_t)NB * 256 * HWS];
__device__ __align__(16) __half g_vT[(size_t)NB * 256 * HWS];
__device__ __align__(16) __nv_bfloat16 g_wsplit[(size_t)384 * KP];       // [m][hi|lo]
__device__ __align__(16) __nv_bfloat16 g_xt[(size_t)NB * HWS * KP];      // [b][p][hi|lo]

// single TU-wide dynamic smem symbol (char; cast per-kernel)
extern __shared__ __align__(1024) char smem_raw[];

static __device__ __forceinline__ uint32_t sw128(uint32_t off) {
    return off ^ ((off >> 3) & 0x70);
}
static __device__ __forceinline__ uint32_t sw256(uint32_t off) {
    return off ^ (((off >> 8) & 7) << 4);
}
__device__ __forceinline__ uint32_t smem_u32(const void* p) {
    uint32_t a;
    asm("{ .reg .u64 t; cvta.to.shared.u64 t, %1; cvt.u32.u64 %0, t; }"
        : "=r"(a) : "l"(p));
    return a;
}
__device__ __forceinline__ void ldmatrix_x4(uint32_t& r0, uint32_t& r1,
                                            uint32_t& r2, uint32_t& r3, uint32_t addr) {
    asm volatile("ldmatrix.sync.aligned.m8n8.x4.shared.b16 {%0,%1,%2,%3}, [%4];"
                 : "=r"(r0), "=r"(r1), "=r"(r2), "=r"(r3) : "r"(addr));
}
__device__ __forceinline__ void ldmatrix_x4_trans(uint32_t& r0, uint32_t& r1,
                                                  uint32_t& r2, uint32_t& r3, uint32_t addr) {
    asm volatile("ldmatrix.sync.aligned.m8n8.x4.trans.shared.b16 {%0,%1,%2,%3}, [%4];"
                 : "=r"(r0), "=r"(r1), "=r"(r2), "=r"(r3) : "r"(addr));
}
__device__ __forceinline__ void mma_bf16(float& d0, float& d1, float& d2, float& d3,
                                         uint32_t a0, uint32_t a1, uint32_t a2, uint32_t a3,
                                         uint32_t b0, uint32_t b1) {
    asm volatile("mma.sync.aligned.m16n8k16.row.col.f32.bf16.bf16.f32 "
                 "{%0,%1,%2,%3}, {%4,%5,%6,%7}, {%8,%9}, {%0,%1,%2,%3};"
                 : "+f"(d0), "+f"(d1), "+f"(d2), "+f"(d3)
                 : "r"(a0), "r"(a1), "r"(a2), "r"(a3), "r"(b0), "r"(b1));
}
__device__ __forceinline__ void mma_f16(float& d0, float& d1, float& d2, float& d3,
                                        uint32_t a0, uint32_t a1, uint32_t a2, uint32_t a3,
                                        uint32_t b0, uint32_t b1) {
    asm volatile("mma.sync.aligned.m16n8k16.row.col.f32.f16.f16.f32 "
                 "{%0,%1,%2,%3}, {%4,%5,%6,%7}, {%8,%9}, {%0,%1,%2,%3};"
                 : "+f"(d0), "+f"(d1), "+f"(d2), "+f"(d3)
                 : "r"(a0), "r"(a1), "r"(a2), "r"(a3), "r"(b0), "r"(b1));
}
#define CP_ASYNC16(dst, src) \
    asm volatile("cp.async.cg.shared.global [%0], [%1], 16;" :: "r"(dst), "l"(src))
#define CP_COMMIT() asm volatile("cp.async.commit_group;" ::: "memory")
#define CP_WAIT1()  asm volatile("cp.async.wait_group 1;" ::: "memory")
#define CP_WAIT0()  asm volatile("cp.async.wait_group 0;" ::: "memory")

// ---------------------------------------------------------------------------
// prep_w: W' bf16 [384][512]; rows 0-255 Wv, 256-287 Wq, 288-319 Wk, 320-383 0
// ---------------------------------------------------------------------------
__global__ void prep_w_kernel(const float* __restrict__ Wq, const float* __restrict__ Wk,
                              const float* __restrict__ Wv)
{
    const int m = blockIdx.x;
    const int c = threadIdx.x;
    float w = 0.0f;
    if (m < 256)      w = Wv[m * 256 + c];
    else if (m < 288) w = Wq[(m - 256) * 256 + c];
    else if (m < 320) w = Wk[(m - 288) * 256 + c];
    __nv_bfloat16 hi = __float2bfloat16(w);
    __nv_bfloat16 lo = __float2bfloat16(w - __bfloat162float(hi));
    g_wsplit[(size_t)m * KP + c]       = hi;
    g_wsplit[(size_t)m * KP + 256 + c] = lo;
}

// ---------------------------------------------------------------------------
// prep_x: XT' bf16 [b][p][512]: cols [0:256)=hi, [256:512)=lo
// ---------------------------------------------------------------------------
__global__ void prep_x_kernel(const float* __restrict__ x)
{
    __shared__ float sm[64][65];
    const int b = blockIdx.z, ct = blockIdx.y, pt = blockIdx.x;
    const int c0 = ct * 64, p0 = pt * 64;
    const int t = threadIdx.x;
    const int pj = t & 63, ci0 = t >> 6;
    const float* xb = x + ((size_t)b * 256 + c0) * HWS + p0;
    #pragma unroll
    for (int i = 0; i < 16; i++) {
        int ci = ci0 + i * 4;
        sm[ci][pj] = xb[(size_t)ci * HWS + pj];
    }
    __syncthreads();
    const int cp = t & 31, pl = t >> 5;
    #pragma unroll
    for (int i = 0; i < 8; i++) {
        int p = pl + i * 8;
        float f0 = sm[2 * cp][p], f1 = sm[2 * cp + 1][p];
        __nv_bfloat16 h0 = __float2bfloat16(f0), h1 = __float2bfloat16(f1);
        __nv_bfloat16 l0 = __float2bfloat16(f0 - __bfloat162float(h0));
        __nv_bfloat16 l1 = __float2bfloat16(f1 - __bfloat162float(h1));
        __nv_bfloat162 hp; hp.x = h0; hp.y = h1;
        __nv_bfloat162 lp; lp.x = l0; lp.y = l1;
        __nv_bfloat16* row = g_xt + ((size_t)b * HWS + p0 + p) * KP;
        *(__nv_bfloat162*)(row + c0 + 2 * cp)       = hp;
        *(__nv_bfloat162*)(row + 256 + c0 + 2 * cp) = lp;
    }
}

// ---------------------------------------------------------------------------
// proj_mma: 2-stage cp.async double-buffered bf16 mma GEMM; epilogue writes
// pre-split operand planes. mt==2 blocks: warp_m==1 rows are zero padding ->
// those warps skip the mma mainloop (tensor pipe is shared; -16.7% work).
// ---------------------------------------------------------------------------
__constant__ int ACH[12] = {0, 1, 2, 3, 0, 1, 2, 3, 4, 5, 6, 7};
__constant__ int BCH[12] = {0, 1, 2, 3, 4, 5, 6, 7, 0, 1, 2, 3};

__global__ void __launch_bounds__(256) proj_mma_kernel(
    const float* __restrict__ bq, const float* __restrict__ bk,
    const float* __restrict__ bv)
{
    char* smem = smem_raw;
    const uint32_t smem_base = smem_u32(smem);
    const int tid = threadIdx.x;
    const int wid = tid >> 5, lane = tid & 31;
    const int warp_m = wid & 1;
    const int warp_n = wid >> 1;
    const int pt = blockIdx.x, mt = blockIdx.y, b = blockIdx.z;
    const bool mma_active = (mt < 2) || (warp_m == 0);

    const char* Abase = (const char*)(g_wsplit + (size_t)mt * 128 * KP);
    const char* Bbase = (const char*)(g_xt + ((size_t)b * HWS + pt * 128) * KP);

    float acc[4][4][4];
    #pragma unroll
    for (int i = 0; i < 4; i++)
        #pragma unroll
        for (int j = 0; j < 4; j++)
            #pragma unroll
            for (int k = 0; k < 4; k++) acc[i][j][k] = 0.0f;

    const int a_row_in = lane & 15;
    const int a_kseg   = (lane >> 4) << 4;
    const int b_row_in = (lane & 7) + ((lane >> 4) << 3);
    const int b_kseg   = ((lane >> 3) & 1) << 4;

    const int ld_row = tid >> 3, ld_seg = tid & 7;

    auto issue = [&](int ch, int st) {
        const size_t a0b = (size_t)ACH[ch] * 128;
        const size_t b0b = (size_t)BCH[ch] * 128;
        const uint32_t sb = smem_base + st * 32768;
        #pragma unroll
        for (int r = 0; r < 4; r++) {
            int row = ld_row + r * 32;
            uint32_t so = sw128((uint32_t)(row * 128 + ld_seg * 16));
            CP_ASYNC16(sb + so,         Abase + (size_t)row * (KP * 2) + a0b + ld_seg * 16);
            CP_ASYNC16(sb + 16384 + so, Bbase + (size_t)row * (KP * 2) + b0b + ld_seg * 16);
        }
    };

    issue(0, 0);
    CP_COMMIT();

    for (int ch = 0; ch < 12; ch++) {
        const int st = ch & 1;
        if (ch + 1 < 12) issue(ch + 1, st ^ 1);
        CP_COMMIT();
        CP_WAIT1();
        __syncthreads();

        if (mma_active) {
            const uint32_t sA_u = smem_base + st * 32768;
            const uint32_t sB_u = sA_u + 16384;
            #pragma unroll
            for (int kk = 0; kk < 4; kk++) {
                uint32_t af[4][4];
                #pragma unroll
                for (int mi = 0; mi < 4; mi++) {
                    int row = warp_m * 64 + mi * 16 + a_row_in;
                    ldmatrix_x4(af[mi][0], af[mi][1], af[mi][2], af[mi][3],
                                sA_u + sw128((uint32_t)(row * 128 + kk * 32 + a_kseg)));
                }
                uint32_t bf[2][4];
                #pragma unroll
                for (int ni16 = 0; ni16 < 2; ni16++) {
                    int row = warp_n * 32 + ni16 * 16 + b_row_in;
                    ldmatrix_x4(bf[ni16][0], bf[ni16][1], bf[ni16][2], bf[ni16][3],
                                sB_u + sw128((uint32_t)(row * 128 + kk * 32 + b_kseg)));
                }
                #pragma unroll
                for (int mi = 0; mi < 4; mi++)
                    #pragma unroll
                    for (int ni = 0; ni < 4; ni++)
                        mma_bf16(acc[mi][ni][0], acc[mi][ni][1], acc[mi][ni][2], acc[mi][ni][3],
                                 af[mi][0], af[mi][1], af[mi][2], af[mi][3],
                                 bf[ni >> 1][(ni & 1) * 2 + 0], bf[ni >> 1][(ni & 1) * 2 + 1]);
            }
        }
        __syncthreads();
    }

    const int p0 = pt * 128 + warp_n * 32 + 2 * (lane & 3);
    #pragma unroll
    for (int mi = 0; mi < 4; mi++) {
        #pragma unroll
        for (int half = 0; half < 2; half++) {
            int m = mt * 128 + warp_m * 64 + mi * 16 + (lane >> 2) + half * 8;
            #pragma unroll
            for (int ni = 0; ni < 4; ni++) {
                float v0 = acc[mi][ni][half * 2 + 0];
                float v1 = acc[mi][ni][half * 2 + 1];
                int p = p0 + ni * 8;
                if (m < 256) {
                    float bias = bv[m];
                    __half2 hv = __floats2half2_rn(v0 + bias, v1 + bias);
                    *(__half2*)&g_v[((size_t)b * 256 + m) * HWS + p] = hv;
                } else if (m < 320) {
                    const bool isq = (m < 288);
                    int c = isq ? (m - 256) : (m - 288);
                    float bias = isq ? bq[c] : bk[c];
                    float f0 = v0 + bias, f1 = v1 + bias;
                    __nv_bfloat16 h0 = __float2bfloat16(f0), h1 = __float2bfloat16(f1);
                    __nv_bfloat16 l0 = __float2bfloat16(f0 - __bfloat162float(h0));
                    __nv_bfloat16 l1 = __float2bfloat16(f1 - __bfloat162float(h1));
                    __nv_bfloat162 hp; hp.x = h0; hp.y = h1;
                    __nv_bfloat162 lp; lp.x = l0; lp.y = l1;
                    size_t off = ((size_t)b * 32 + c) * HWS + p;
                    if (isq) {
                        *(__nv_bfloat162*)&g_qhi[off] = hp;
                        *(__nv_bfloat162*)&g_qlo[off] = lp;
                    } else {
                        *(__nv_bfloat162*)&g_khi[off] = hp;
                        *(__nv_bfloat162*)&g_klo[off] = lp;
                    }
                }
            }
        }
    }
}

// ---------------------------------------------------------------------------
// transpose: 16-bit planes [H][W] -> [W][H]; 64x64 tiles, uint32 vectorized.
// smem row stride 70 uint16 = 140B: 4B aligned, bank pattern 35*l mod 32
// (gcd(35,32)=1) -> conflict-free column reads.
// ---------------------------------------------------------------------------
__global__ void transpose_kernel()
{
    __shared__ uint16_t sm[64][70];
    const int plane = blockIdx.z;
    const uint16_t* src;
    uint16_t* dst;
    if (plane < 512) {
        int t = plane >> 7, ch = plane & 127;
        const __nv_bfloat16* s;
        __nv_bfloat16* d;
        switch (t) {
            case 0:  s = g_qhi; d = g_qhiT; break;
            case 1:  s = g_qlo; d = g_qloT; break;
            case 2:  s = g_khi; d = g_khiT; break;
            default: s = g_klo; d = g_kloT; break;
        }
        src = (const uint16_t*)(s + (size_t)ch * HWS);
        dst = (uint16_t*)(d + (size_t)ch * HWS);
    } else {
        int ch = plane - 512;
        src = (const uint16_t*)(g_v + (size_t)ch * HWS);
        dst = (uint16_t*)(g_vT + (size_t)ch * HWS);
    }
    const int ti = blockIdx.y * 64, tj = blockIdx.x * 64;   // ti = h0, tj = w0
    const int t = threadIdx.x;
    const int cw = (t & 31) * 2, r0 = t >> 5;
    #pragma unroll
    for (int p = 0; p < 8; p++) {
        int r = r0 + p * 8;
        *(uint32_t*)&sm[r][cw] = *(const uint32_t*)&src[(size_t)(ti + r) * WW + tj + cw];
    }
    __syncthreads();
    const int ch2 = (t & 31) * 2, w0 = t >> 5;
    #pragma unroll
    for (int p = 0; p < 8; p++) {
        int w = w0 + p * 8;
        uint32_t v = (uint32_t)sm[ch2][w] | ((uint32_t)sm[ch2 + 1][w] << 16);
        *(uint32_t*)&dst[(size_t)(tj + w) * HH + ti + ch2] = v;
    }
}

// ---------------------------------------------------------------------------
// Tensor-core criss-cross attention; operands pre-split; BOTH phases'
// cp.async issued upfront (double-buffered A/B/V) so phase-1 loads hide
// under phase-0 compute.
// smem: [0,32K)       P fp16 [g][j], 256B rows, sw256
//       [32K,48K)     V0, [48K,64K) V1  fp16 [c][g] sw256
//       [64K,72K)     A0, [72K,80K) A1  bf16 [c'][g] sw256
//       [80K,88K)     B0, [88K,96K) B1
//       [96K,97K)     ssum[2][128] fp32
// ---------------------------------------------------------------------------
#define AT_P    0
#define AT_V0   32768
#define AT_V1   49152
#define AT_A0   65536
#define AT_A1   73728
#define AT_B0   81920
#define AT_B1   90112
#define AT_SSUM 98304
#define AT_SMEM (98304 + 1024)

__global__ void __launch_bounds__(256, 2) attn_kernel(
    const float* __restrict__ x, const float* __restrict__ gamma,
    float* __restrict__ out)
{
    char* smem = smem_raw;
    float* ssum = (float*)(smem + AT_SSUM);

    const int i  = blockIdx.x;
    const int bh = blockIdx.y;
    const int b = bh >> 2, h = bh & 3;
    const int tid = threadIdx.x;
    const int wid = tid >> 5, lane = tid & 31;

    const uint32_t smb  = smem_u32(smem);
    const uint32_t sP_u = smb + AT_P;

    // V (B-operand, non-trans) lane addressing
    const int b_row_in = (lane & 7) + ((lane >> 4) << 3);
    const int b_kseg   = ((lane >> 3) & 1) << 4;
    // trans-ldmatrix lane addressing (A-style)
    const int tr_row_a = (lane & 7) + (((lane >> 4) & 1) << 3);
    const int tr_col_a = ((lane >> 3) & 1) << 3;
    // trans-ldmatrix lane addressing (B-style)
    const int tr_row_b = (lane & 7) + (((lane >> 3) & 1) << 3);
    const int tr_col_b = ((lane >> 4) & 1) << 3;

    const int em = wid & 1, en = wid >> 1;

    const int qkc0 = (b * 32 + h * 8);
    const int vc0  = (b * 256 + h * 64);
    const int loff = i * 128;

    // zero pad rows 24-31 of A0/A1/B0/B1 (persist across phases)
    #pragma unroll
    for (int z = 0; z < 2; z++) {
        int idx = tid + z * 256;                 // 0..511
        int bufsel = idx >> 7;                   // 0:A0 1:A1 2:B0 3:B1
        int r = 24 + ((idx >> 4) & 7), chunk = idx & 15;
        uint32_t base = (bufsel == 0) ? AT_A0 : (bufsel == 1) ? AT_A1
                       : (bufsel == 2) ? AT_B0 : AT_B1;
        *(uint4*)(smem + base + sw256((uint32_t)(r * 256 + chunk * 16))) =
            make_uint4(0, 0, 0, 0);
    }

    // ---- issue BOTH phases' cp.async upfront (2 groups) ----
    #pragma unroll
    for (int ph = 0; ph < 2; ph++) {
        const __nv_bfloat16* Khi = ph ? g_khiT : g_khi;
        const __nv_bfloat16* Klo = ph ? g_kloT : g_klo;
        const __nv_bfloat16* Qhi = ph ? g_qhiT : g_qhi;
        const __nv_bfloat16* Qlo = ph ? g_qloT : g_qlo;
        const __half*        Vp  = ph ? g_vT   : g_v;
        const uint32_t aU = smb + (ph ? AT_A1 : AT_A0);
        const uint32_t bU = smb + (ph ? AT_B1 : AT_B0);
        const uint32_t vU = smb + (ph ? AT_V1 : AT_V0);
        #pragma unroll
        for (int it = 0; it < 3; it++) {          // A+B: 48 rows x 16 chunks
            int idx = tid + it * 256;
            int rr2 = idx >> 4, chunk = idx & 15;
            int tile = rr2 >= 24;
            int r = tile ? (rr2 - 24) : rr2;
            int c = r & 7;
            const __nv_bfloat16* src;
            if (!tile) src = (r < 16) ? Khi : Klo;
            else       src = (r >= 8 && r < 16) ? Qlo : Qhi;
            const char* gsrc = (const char*)(src + (size_t)(qkc0 + c) * HWS + loff) + chunk * 16;
            uint32_t dst = (tile ? bU : aU) + sw256((uint32_t)(r * 256 + chunk * 16));
            CP_ASYNC16(dst, gsrc);
        }
        #pragma unroll
        for (int it = 0; it < 4; it++) {          // V: 64 rows x 16 chunks
            int idx = tid + it * 256;
            int c = idx >> 4, chunk = idx & 15;
            const char* gsrc = (const char*)(Vp + (size_t)(vc0 + c) * HWS + loff) + chunk * 16;
            CP_ASYNC16(vU + sw256((uint32_t)(c * 256 + chunk * 16)), gsrc);
        }
        CP_COMMIT();
    }

    float acc[8][4];
    #pragma unroll
    for (int ni = 0; ni < 8; ni++)
        #pragma unroll
        for (int k = 0; k < 4; k++) acc[ni][k] = 0.0f;

    for (int phase = 0; phase < 2; phase++) {
        const uint32_t sA_u = smb + (phase ? AT_A1 : AT_A0);
        const uint32_t sB_u = smb + (phase ? AT_B1 : AT_B0);
        const uint32_t sV_u = smb + (phase ? AT_V1 : AT_V0);
        if (phase == 0) { CP_WAIT1(); } else { CP_WAIT0(); }
        __syncthreads();

        // ---- energy mma: A,B via trans-ldmatrix from [c'][g] tiles ----
        float ef[4][4][4];
        #pragma unroll
        for (int mi = 0; mi < 4; mi++)
            #pragma unroll
            for (int ni = 0; ni < 4; ni++)
                #pragma unroll
                for (int k = 0; k < 4; k++) ef[mi][ni][k] = 0.0f;
        #pragma unroll
        for (int ks = 0; ks < 2; ks++) {
            uint32_t af[4][4];
            #pragma unroll
            for (int mi = 0; mi < 4; mi++) {
                int row = ks * 16 + tr_row_a;
                int col = em * 64 + mi * 16 + tr_col_a;
                ldmatrix_x4_trans(af[mi][0], af[mi][1], af[mi][2], af[mi][3],
                                  sA_u + sw256((uint32_t)(row * 256 + col * 2)));
            }
            uint32_t bfr[2][4];
            #pragma unroll
            for (int n16 = 0; n16 < 2; n16++) {
                int row = ks * 16 + tr_row_b;
                int col = en * 32 + n16 * 16 + tr_col_b;
                ldmatrix_x4_trans(bfr[n16][0], bfr[n16][1], bfr[n16][2], bfr[n16][3],
                                  sB_u + sw256((uint32_t)(row * 256 + col * 2)));
            }
            #pragma unroll
            for (int mi = 0; mi < 4; mi++)
                #pragma unroll
                for (int ni = 0; ni < 4; ni++)
                    mma_bf16(ef[mi][ni][0], ef[mi][ni][1], ef[mi][ni][2], ef[mi][ni][3],
                             af[mi][0], af[mi][1], af[mi][2], af[mi][3],
                             bfr[ni >> 1][(ni & 1) * 2 + 0], bfr[ni >> 1][(ni & 1) * 2 + 1]);
        }

        // ---- exp in registers + per-j column sums ----
        float psum[4][2];
        #pragma unroll
        for (int ni = 0; ni < 4; ni++) { psum[ni][0] = 0.0f; psum[ni][1] = 0.0f; }
        #pragma unroll
        for (int mi = 0; mi < 4; mi++)
            #pragma unroll
            for (int ni = 0; ni < 4; ni++) {
                ef[mi][ni][0] = __expf(ef[mi][ni][0]);
                ef[mi][ni][1] = __expf(ef[mi][ni][1]);
                ef[mi][ni][2] = __expf(ef[mi][ni][2]);
                ef[mi][ni][3] = __expf(ef[mi][ni][3]);
                psum[ni][0] += ef[mi][ni][0] + ef[mi][ni][2];
                psum[ni][1] += ef[mi][ni][1] + ef[mi][ni][3];
            }
        #pragma unroll
        for (int ni = 0; ni < 4; ni++) {
            #pragma unroll
            for (int d = 4; d <= 16; d <<= 1) {
                psum[ni][0] += __shfl_xor_sync(0xffffffffu, psum[ni][0], d);
                psum[ni][1] += __shfl_xor_sync(0xffffffffu, psum[ni][1], d);
            }
        }
        if ((lane >> 2) == 0) {
            #pragma unroll
            for (int ni = 0; ni < 4; ni++) {
                int j0 = en * 32 + ni * 8 + (lane & 3) * 2;
                *(float2*)&ssum[em * 128 + j0] = make_float2(psum[ni][0], psum[ni][1]);
            }
        }
        __syncthreads();

        // ---- normalize + store P fp16 [g][j] ----
        #pragma unroll
        for (int ni = 0; ni < 4; ni++) {
            int j0 = en * 32 + ni * 8 + (lane & 3) * 2;
            float2 sa = *(float2*)&ssum[j0];
            float2 sb = *(float2*)&ssum[128 + j0];
            float is0 = 1.0f / (sa.x + sb.x);
            float is1 = 1.0f / (sa.y + sb.y);
            #pragma unroll
            for (int mi = 0; mi < 4; mi++) {
                int g0 = em * 64 + mi * 16 + (lane >> 2);
                __half2 p0 = __floats2half2_rn(ef[mi][ni][0] * is0, ef[mi][ni][1] * is1);
                __half2 p1 = __floats2half2_rn(ef[mi][ni][2] * is0, ef[mi][ni][3] * is1);
                *(uint32_t*)(smem + AT_P + sw256((uint32_t)(g0 * 256 + j0 * 2)))       = *(uint32_t*)&p0;
                *(uint32_t*)(smem + AT_P + sw256((uint32_t)((g0 + 8) * 256 + j0 * 2))) = *(uint32_t*)&p1;
            }
        }
        __syncthreads();

        // ---- O mma: A = P (m=j, k=g, trans), B = V (n=c, k=g) ----
        {
            #pragma unroll
            for (int ks = 0; ks < 8; ks++) {
                uint32_t af[4];
                {
                    int row = ks * 16 + tr_row_a;
                    int col = wid * 16 + tr_col_a;
                    ldmatrix_x4_trans(af[0], af[1], af[2], af[3],
                                      sP_u + sw256((uint32_t)(row * 256 + col * 2)));
                }
                uint32_t bfr[4][4];
                #pragma unroll
                for (int n16 = 0; n16 < 4; n16++) {
                    int row = n16 * 16 + b_row_in;
                    ldmatrix_x4(bfr[n16][0], bfr[n16][1], bfr[n16][2], bfr[n16][3],
                                sV_u + sw256((uint32_t)(row * 256 + ks * 32) + (uint32_t)b_kseg));
                }
                #pragma unroll
                for (int n16 = 0; n16 < 4; n16++)
                    #pragma unroll
                    for (int sub = 0; sub < 2; sub++)
                        mma_f16(acc[n16 * 2 + sub][0], acc[n16 * 2 + sub][1],
                                acc[n16 * 2 + sub][2], acc[n16 * 2 + sub][3],
                                af[0], af[1], af[2], af[3],
                                bfr[n16][sub * 2 + 0], bfr[n16][sub * 2 + 1]);
            }
        }
        __syncthreads();
    }

    // ---- epilogue ----
    const float gm = gamma[0];
    const size_t bch = (size_t)b * 256 + h * 64;
    const int jb = wid * 16 + (lane >> 2);
    #pragma unroll
    for (int ni = 0; ni < 8; ni++) {
        int c0 = ni * 8 + (lane & 3) * 2;
        #pragma unroll
        for (int hf = 0; hf < 2; hf++) {
            int j = jb + hf * 8;
            size_t off0 = ((bch + c0) * HH + i) * WW + j;
            size_t off1 = off0 + HWS;
            out[off0] = gm * acc[ni][hf * 2 + 0] + x[off0];
            out[off1] = gm * acc[ni][hf * 2 + 1] + x[off1];
        }
    }
}

// ---------------------------------------------------------------------------
extern "C" void kernel_launch(void* const* d_in, const int* in_sizes, int n_in,
                              void* d_out, int out_size)
{
    const float* x     = (const float*)d_in[0];
    const float* Wq    = (const float*)d_in[1];
    const float* bq    = (const float*)d_in[2];
    const float* Wk    = (const float*)d_in[3];
    const float* bk    = (const float*)d_in[4];
    const float* Wv    = (const float*)d_in[5];
    const float* bv    = (const float*)d_in[6];
    const float* gamma = (const float*)d_in[7];
    float* out = (float*)d_out;

    cudaFuncSetAttribute(attn_kernel, cudaFuncAttributeMaxDynamicSharedMemorySize,
                         AT_SMEM);
    cudaFuncSetAttribute(proj_mma_kernel, cudaFuncAttributeMaxDynamicSharedMemorySize,
                         65536);

    prep_w_kernel<<<384, 256>>>(Wq, Wk, Wv);
    prep_x_kernel<<<dim3(256, 4, NB), 256>>>(x);
    proj_mma_kernel<<<dim3(128, 3, NB), 256, 65536>>>(bq, bk, bv);
    transpose_kernel<<<dim3(2, 2, 1536), 256>>>();
    attn_kernel<<<dim3(HH, NB * 4), 256, AT_SMEM>>>(x, gamma, out);
}